// round 7
// baseline (speedup 1.0000x reference)
#include <cuda_runtime.h>
#include <cuda_bf16.h>
#include <math.h>

// Problem constants (fixed by the reference setup).
#define NNODES 100000
#define NEDGES 1600000
#define F_IN   256
#define F_HID  128
#define F_OUT  40

typedef unsigned long long u64;

// ---------------------------------------------------------------------------
// Packed f32x2 helpers (Blackwell double-rate fp32 path; ptxas never auto-fuses)
// ---------------------------------------------------------------------------
__device__ __forceinline__ u64 pack2(float lo, float hi) {
    u64 r;
    asm("mov.b64 %0, {%1, %2};" : "=l"(r) : "r"(__float_as_uint(lo)), "r"(__float_as_uint(hi)));
    return r;
}
__device__ __forceinline__ void unpack2(u64 v, float& lo, float& hi) {
    unsigned a, b;
    asm("mov.b64 {%0, %1}, %2;" : "=r"(a), "=r"(b) : "l"(v));
    lo = __uint_as_float(a); hi = __uint_as_float(b);
}
__device__ __forceinline__ u64 fma2(u64 a, u64 b, u64 c) {
    u64 d;
    asm("fma.rn.f32x2 %0, %1, %2, %3;" : "=l"(d) : "l"(a), "l"(b), "l"(c));
    return d;
}

// ---------------------------------------------------------------------------
// Scratch (device globals; no cudaMalloc allowed)
// ---------------------------------------------------------------------------
__device__ float g_h [NNODES * F_HID];
__device__ float g_x0[NNODES * F_HID];
__device__ float g_xa[NNODES * F_HID];
__device__ float g_xb[NNODES * F_HID];
__device__ int   g_deg   [NNODES];
__device__ int   g_rowptr[NNODES + 1];
__device__ int   g_cursor[NNODES];
__device__ int2  g_esw   [NEDGES];       // (src, bits(edge_weight)) sorted by tgt

// ---------------------------------------------------------------------------
// CSR build
// ---------------------------------------------------------------------------
__global__ void zero_int_kernel(int* p, int n) {
    int i = blockIdx.x * blockDim.x + threadIdx.x;
    if (i < n) p[i] = 0;
}

__global__ void hist_kernel(const int* __restrict__ tgt, int* __restrict__ deg, int e) {
    int i = blockIdx.x * blockDim.x + threadIdx.x;
    if (i < e) atomicAdd(&deg[tgt[i]], 1);
}

// Single-block exclusive scan over deg[n] -> rowptr[n+1], cursor[n].
__global__ void scan_kernel(const int* __restrict__ deg, int* __restrict__ rowptr,
                            int* __restrict__ cursor, int n) {
    __shared__ int sums[1024];
    int t = threadIdx.x;
    const int CH = (n + 1023) >> 10;
    int beg = t * CH;
    int endi = beg + CH; if (endi > n) endi = n;
    int s = 0;
    for (int i = beg; i < endi; ++i) s += deg[i];
    sums[t] = s;
    __syncthreads();
    for (int off = 1; off < 1024; off <<= 1) {
        int v = (t >= off) ? sums[t - off] : 0;
        __syncthreads();
        sums[t] += v;
        __syncthreads();
    }
    int run = (t == 0) ? 0 : sums[t - 1];
    for (int i = beg; i < endi; ++i) {
        rowptr[i] = run;
        cursor[i] = run;
        run += deg[i];
    }
    if (t == 0) rowptr[n] = sums[1023];
}

__global__ void fill_kernel(const int* __restrict__ src, const int* __restrict__ tgt,
                            const float* __restrict__ ew, int* __restrict__ cursor,
                            int2* __restrict__ esw, int e) {
    int i = blockIdx.x * blockDim.x + threadIdx.x;
    if (i < e) {
        int p = atomicAdd(&cursor[tgt[i]], 1);
        esw[p] = make_int2(src[i], __float_as_int(ew[i]));
    }
}

// ---------------------------------------------------------------------------
// Dense GEMM with fused bias using packed f32x2 FMA.
// C[M,N] = A[M,K] @ W[K,N] + b.  BM=128, BK=16, 256 threads.
// Accumulators paired along M so A-operand f32x2 pairs come directly from
// contiguous LDS.128 loads (no pack instructions for A).
// ---------------------------------------------------------------------------
template<int K, int N, int BN>
__global__ void __launch_bounds__(256)
gemm_bias_kernel(const float* __restrict__ A, const float* __restrict__ W,
                 const float* __restrict__ bias, float* __restrict__ C, int M) {
    constexpr int BM = 128, BK = 16, TN = 8;
    constexpr int COLT = BN / TN;           // 16 (BN=128) or 8 (BN=64)
    constexpr int ROWT = 256 / COLT;        // 16 or 32
    constexpr int TM   = BM / ROWT;         // 8 or 4
    constexpr int TMH  = TM / 2;            // 4 or 2
    constexpr int ALOADS = (BM * BK) / (4 * 256);   // 2
    constexpr int BLOADS = (BK * BN) / (4 * 256);   // 2 or 1

    __shared__ __align__(16) float As[BK][BM];
    __shared__ __align__(16) float Bs[BK][BN];

    const int tid  = threadIdx.x;
    const int row0 = blockIdx.x * BM;
    const int tr   = tid / COLT;
    const int tc   = tid % COLT;

    u64 acc2[TMH][TN];     // acc2[i2][j] = (C[2*i2][j], C[2*i2+1][j]) packed
#pragma unroll
    for (int i = 0; i < TMH; ++i)
#pragma unroll
        for (int j = 0; j < TN; ++j) acc2[i][j] = 0ull;

    for (int kk = 0; kk < K; kk += BK) {
        // ---- load A tile (transposed into As[k][m]) ----
#pragma unroll
        for (int i = 0; i < ALOADS; ++i) {
            int lin = tid + i * 256;
            int r   = lin >> 2;            // BK/4 == 4 float4 per row
            int c4  = lin & 3;
            int grow = row0 + r;
            float4 v = make_float4(0.f, 0.f, 0.f, 0.f);
            if (grow < M)
                v = *(const float4*)&A[(size_t)grow * K + kk + c4 * 4];
            As[c4 * 4 + 0][r] = v.x;
            As[c4 * 4 + 1][r] = v.y;
            As[c4 * 4 + 2][r] = v.z;
            As[c4 * 4 + 3][r] = v.w;
        }
        // ---- load B tile ----
#pragma unroll
        for (int i = 0; i < BLOADS; ++i) {
            int lin = tid + i * 256;
            int r   = lin / (BN / 4);
            int c   = (lin % (BN / 4)) * 4;
            float4 v = make_float4(0.f, 0.f, 0.f, 0.f);
            if (c < N)
                v = *(const float4*)&W[(size_t)(kk + r) * N + c];
            *(float4*)&Bs[r][c] = v;
        }
        __syncthreads();

#pragma unroll
        for (int k = 0; k < BK; ++k) {
            // A pairs: contiguous rows (m, m+1) arrive already-packed in 64-bit halves.
            u64 ap[TMH];
#pragma unroll
            for (int i = 0; i < TMH; i += 2) {
                ulonglong2 v = *(const ulonglong2*)&As[k][tr * TM + 2 * i];
                ap[i]     = v.x;
                ap[i + 1] = v.y;
            }
            // B scalars -> broadcast packs
            float b[TN];
#pragma unroll
            for (int j = 0; j < TN; j += 4) {
                float4 t = *(const float4*)&Bs[k][tc * TN + j];
                b[j] = t.x; b[j + 1] = t.y; b[j + 2] = t.z; b[j + 3] = t.w;
            }
            u64 bb[TN];
#pragma unroll
            for (int j = 0; j < TN; ++j) bb[j] = pack2(b[j], b[j]);

#pragma unroll
            for (int j = 0; j < TN; ++j)
#pragma unroll
                for (int i = 0; i < TMH; ++i)
                    acc2[i][j] = fma2(ap[i], bb[j], acc2[i][j]);
        }
        __syncthreads();
    }

    // ---- epilogue: unpack, add bias, store ----
#pragma unroll
    for (int i2 = 0; i2 < TMH; ++i2) {
        float lo[TN], hi[TN];
#pragma unroll
        for (int j = 0; j < TN; ++j) unpack2(acc2[i2][j], lo[j], hi[j]);

#pragma unroll
        for (int half = 0; half < 2; ++half) {
            const float* v = half ? hi : lo;
            int grow = row0 + tr * TM + 2 * i2 + half;
            if (grow >= M) continue;
#pragma unroll
            for (int j = 0; j < TN; j += 4) {
                int c = tc * TN + j;
                if (c + 3 < N) {
                    float4 o;
                    o.x = v[j + 0] + bias[c + 0];
                    o.y = v[j + 1] + bias[c + 1];
                    o.z = v[j + 2] + bias[c + 2];
                    o.w = v[j + 3] + bias[c + 3];
                    *(float4*)&C[(size_t)grow * N + c] = o;
                } else {
#pragma unroll
                    for (int jj = 0; jj < 4; ++jj)
                        if (c + jj < N)
                            C[(size_t)grow * N + c + jj] = v[j + jj] + bias[c + jj];
                }
            }
        }
    }
}

// ---------------------------------------------------------------------------
// Aggregation (gather-CSR), F=128, warp per node, float4 per lane, 4x MLP.
// MODE 0: relu(sum);  MODE 1: relu(sum) + res
// ---------------------------------------------------------------------------
template<int MODE>
__global__ void agg128_kernel(const float* __restrict__ h,
                              const int* __restrict__ rowptr,
                              const int2* __restrict__ esw,
                              const float* __restrict__ res,
                              float* __restrict__ out, int n) {
    int warp = (blockIdx.x * blockDim.x + threadIdx.x) >> 5;
    int lane = threadIdx.x & 31;
    if (warp >= n) return;
    int beg = rowptr[warp];
    int end = rowptr[warp + 1];

    const float4* h4 = (const float4*)h;
    float4 acc = make_float4(0.f, 0.f, 0.f, 0.f);

    int j = beg;
    for (; j + 3 < end; j += 4) {
        int2 sw0 = __ldg(&esw[j]);
        int2 sw1 = __ldg(&esw[j + 1]);
        int2 sw2 = __ldg(&esw[j + 2]);
        int2 sw3 = __ldg(&esw[j + 3]);
        float w0 = __int_as_float(sw0.y);
        float w1 = __int_as_float(sw1.y);
        float w2 = __int_as_float(sw2.y);
        float w3 = __int_as_float(sw3.y);
        float4 v0 = __ldg(&h4[(size_t)sw0.x * 32 + lane]);
        float4 v1 = __ldg(&h4[(size_t)sw1.x * 32 + lane]);
        float4 v2 = __ldg(&h4[(size_t)sw2.x * 32 + lane]);
        float4 v3 = __ldg(&h4[(size_t)sw3.x * 32 + lane]);
        acc.x = fmaf(v0.x, w0, acc.x); acc.y = fmaf(v0.y, w0, acc.y);
        acc.z = fmaf(v0.z, w0, acc.z); acc.w = fmaf(v0.w, w0, acc.w);
        acc.x = fmaf(v1.x, w1, acc.x); acc.y = fmaf(v1.y, w1, acc.y);
        acc.z = fmaf(v1.z, w1, acc.z); acc.w = fmaf(v1.w, w1, acc.w);
        acc.x = fmaf(v2.x, w2, acc.x); acc.y = fmaf(v2.y, w2, acc.y);
        acc.z = fmaf(v2.z, w2, acc.z); acc.w = fmaf(v2.w, w2, acc.w);
        acc.x = fmaf(v3.x, w3, acc.x); acc.y = fmaf(v3.y, w3, acc.y);
        acc.z = fmaf(v3.z, w3, acc.z); acc.w = fmaf(v3.w, w3, acc.w);
    }
    for (; j < end; ++j) {
        int2 sw = __ldg(&esw[j]);
        float w = __int_as_float(sw.y);
        float4 v = __ldg(&h4[(size_t)sw.x * 32 + lane]);
        acc.x = fmaf(v.x, w, acc.x); acc.y = fmaf(v.y, w, acc.y);
        acc.z = fmaf(v.z, w, acc.z); acc.w = fmaf(v.w, w, acc.w);
    }

    acc.x = fmaxf(acc.x, 0.f); acc.y = fmaxf(acc.y, 0.f);
    acc.z = fmaxf(acc.z, 0.f); acc.w = fmaxf(acc.w, 0.f);
    if (MODE == 1) {
        float4 r = ((const float4*)res)[(size_t)warp * 32 + lane];
        acc.x += r.x; acc.y += r.y; acc.z += r.z; acc.w += r.w;
    }
    ((float4*)out)[(size_t)warp * 32 + lane] = acc;
}

// ---------------------------------------------------------------------------
// Final aggregation (F=40) fused with log_softmax; writes d_out directly.
// ---------------------------------------------------------------------------
__global__ void agg40_lsm_kernel(const float* __restrict__ h,
                                 const int* __restrict__ rowptr,
                                 const int2* __restrict__ esw,
                                 float* __restrict__ out, int n) {
    int warp = (blockIdx.x * blockDim.x + threadIdx.x) >> 5;
    int lane = threadIdx.x & 31;
    if (warp >= n) return;
    int beg = rowptr[warp];
    int end = rowptr[warp + 1];

    float a0 = 0.f, a1 = 0.f;
    for (int j = beg; j < end; ++j) {
        int2 sw = __ldg(&esw[j]);
        float w = __int_as_float(sw.y);
        const float* hp = h + (size_t)sw.x * F_OUT;
        a0 = fmaf(__ldg(&hp[lane]), w, a0);
        if (lane < 8) a1 = fmaf(__ldg(&hp[32 + lane]), w, a1);
    }

    float m = a0;
    if (lane < 8) m = fmaxf(m, a1);
#pragma unroll
    for (int o = 16; o > 0; o >>= 1)
        m = fmaxf(m, __shfl_xor_sync(0xffffffffu, m, o));

    float s = expf(a0 - m) + ((lane < 8) ? expf(a1 - m) : 0.f);
#pragma unroll
    for (int o = 16; o > 0; o >>= 1)
        s += __shfl_xor_sync(0xffffffffu, s, o);
    float lse = logf(s);

    out[(size_t)warp * F_OUT + lane] = a0 - m - lse;
    if (lane < 8)
        out[(size_t)warp * F_OUT + 32 + lane] = a1 - m - lse;
}

// ---------------------------------------------------------------------------
// Launch
// ---------------------------------------------------------------------------
extern "C" void kernel_launch(void* const* d_in, const int* in_sizes, int n_in,
                              void* d_out, int out_size) {
    const float* x   = (const float*)d_in[0];
    const int*   src = (const int*)  d_in[1];
    const int*   tgt = (const int*)  d_in[2];
    const float* ew  = (const float*)d_in[3];
    const float* W0  = (const float*)d_in[4];
    const float* b0  = (const float*)d_in[5];
    const float* W1  = (const float*)d_in[6];
    const float* b1  = (const float*)d_in[7];
    const float* W2  = (const float*)d_in[8];
    const float* b2  = (const float*)d_in[9];
    const float* W3  = (const float*)d_in[10];
    const float* b3  = (const float*)d_in[11];
    float* out = (float*)d_out;

    float *h, *x0, *xa, *xb;
    int *deg, *rowptr, *cursor;
    int2* esw;
    cudaGetSymbolAddress((void**)&h,      g_h);
    cudaGetSymbolAddress((void**)&x0,     g_x0);
    cudaGetSymbolAddress((void**)&xa,     g_xa);
    cudaGetSymbolAddress((void**)&xb,     g_xb);
    cudaGetSymbolAddress((void**)&deg,    g_deg);
    cudaGetSymbolAddress((void**)&rowptr, g_rowptr);
    cudaGetSymbolAddress((void**)&cursor, g_cursor);
    cudaGetSymbolAddress((void**)&esw,    g_esw);

    const int M = NNODES;
    const int E = NEDGES;

    // ---- CSR build (by target) ----
    zero_int_kernel<<<(M + 255) / 256, 256>>>(deg, M);
    hist_kernel<<<(E + 255) / 256, 256>>>(tgt, deg, E);
    scan_kernel<<<1, 1024>>>(deg, rowptr, cursor, M);
    fill_kernel<<<(E + 255) / 256, 256>>>(src, tgt, ew, cursor, esw, E);

    const int gemm_blocks = (M + 127) / 128;
    const int agg_blocks  = (M + 7) / 8;

    // ---- layer 0 ----
    gemm_bias_kernel<F_IN, F_HID, 128><<<gemm_blocks, 256>>>(x, W0, b0, h, M);
    agg128_kernel<0><<<agg_blocks, 256>>>(h, rowptr, esw, nullptr, x0, M);

    // ---- layer 1 ----
    gemm_bias_kernel<F_HID, F_HID, 128><<<gemm_blocks, 256>>>(x0, W1, b1, h, M);
    agg128_kernel<0><<<agg_blocks, 256>>>(h, rowptr, esw, nullptr, xa, M);

    // ---- layer 2 ----
    gemm_bias_kernel<F_HID, F_HID, 128><<<gemm_blocks, 256>>>(xa, W2, b2, h, M);
    agg128_kernel<1><<<agg_blocks, 256>>>(h, rowptr, esw, x0, xb, M);

    // ---- layer 3 ----
    gemm_bias_kernel<F_HID, F_OUT, 64><<<gemm_blocks, 256>>>(xb, W3, b3, h, M);
    agg40_lsm_kernel<<<agg_blocks, 256>>>(h, rowptr, esw, out, M);
}

// round 9
// speedup vs baseline: 1.2089x; 1.2089x over previous
#include <cuda_runtime.h>
#include <cuda_bf16.h>
#include <math.h>
#include <stdint.h>

// Problem constants (fixed by the reference setup).
#define NNODES 100000
#define NEDGES 1600000
#define F_IN   256
#define F_HID  128
#define F_OUT  40

// ---------------------------------------------------------------------------
// Scratch (device globals; no cudaMalloc allowed)
// ---------------------------------------------------------------------------
__device__ float         g_h  [NNODES * F_HID];     // GEMM output (fp32), stride 128 (or 40 for layer 3)
__device__ float         g_x0 [NNODES * F_HID];     // x0 fp32 (residual)
__device__ __nv_bfloat16 g_xh [NNODES * F_IN];      // input x split hi
__device__ __nv_bfloat16 g_xl [NNODES * F_IN];      // input x split lo
__device__ __nv_bfloat16 g_p0h[NNODES * F_HID];     // activation pair buffer 0
__device__ __nv_bfloat16 g_p0l[NNODES * F_HID];
__device__ __nv_bfloat16 g_p1h[NNODES * F_HID];     // activation pair buffer 1
__device__ __nv_bfloat16 g_p1l[NNODES * F_HID];
// Transposed, padded, split weights: Wt[n][k]
__device__ __nv_bfloat16 g_w0h[128 * 256], g_w0l[128 * 256];
__device__ __nv_bfloat16 g_w1h[128 * 128], g_w1l[128 * 128];
__device__ __nv_bfloat16 g_w2h[128 * 128], g_w2l[128 * 128];
__device__ __nv_bfloat16 g_w3h[ 64 * 128], g_w3l[ 64 * 128];
// CSR
__device__ int  g_deg   [NNODES];
__device__ int  g_rowptr[NNODES + 1];
__device__ int  g_cursor[NNODES];
__device__ int2 g_esw   [NEDGES];

// ---------------------------------------------------------------------------
// Helpers
// ---------------------------------------------------------------------------
__device__ __forceinline__ void split2(float v, __nv_bfloat16& h, __nv_bfloat16& l) {
    h = __float2bfloat16(v);
    l = __float2bfloat16(v - __bfloat162float(h));
}

__device__ __forceinline__ uint32_t pack_bf(__nv_bfloat16 a, __nv_bfloat16 b) {
    return ((uint32_t)__bfloat16_as_ushort(b) << 16) | (uint32_t)__bfloat16_as_ushort(a);
}

__device__ __forceinline__ void ldsm4(uint32_t* d, const void* p) {
    uint32_t a = (uint32_t)__cvta_generic_to_shared(p);
    asm volatile("ldmatrix.sync.aligned.m8n8.x4.shared.b16 {%0,%1,%2,%3}, [%4];\n"
                 : "=r"(d[0]), "=r"(d[1]), "=r"(d[2]), "=r"(d[3]) : "r"(a));
}

__device__ __forceinline__ void mma_bf16(float* c, const uint32_t* a, const uint32_t* b) {
    asm volatile(
        "mma.sync.aligned.m16n8k16.row.col.f32.bf16.bf16.f32 "
        "{%0,%1,%2,%3}, {%4,%5,%6,%7}, {%8,%9}, {%0,%1,%2,%3};\n"
        : "+f"(c[0]), "+f"(c[1]), "+f"(c[2]), "+f"(c[3])
        : "r"(a[0]), "r"(a[1]), "r"(a[2]), "r"(a[3]), "r"(b[0]), "r"(b[1]));
}

// ---------------------------------------------------------------------------
// CSR build
// ---------------------------------------------------------------------------
__global__ void zero_int_kernel(int* p, int n) {
    int i = blockIdx.x * blockDim.x + threadIdx.x;
    if (i < n) p[i] = 0;
}

__global__ void hist_kernel(const int* __restrict__ tgt, int* __restrict__ deg, int e) {
    int i = blockIdx.x * blockDim.x + threadIdx.x;
    if (i < e) atomicAdd(&deg[tgt[i]], 1);
}

__global__ void scan_kernel(const int* __restrict__ deg, int* __restrict__ rowptr,
                            int* __restrict__ cursor, int n) {
    __shared__ int sums[1024];
    int t = threadIdx.x;
    const int CH = (n + 1023) >> 10;
    int beg = t * CH;
    int endi = beg + CH; if (endi > n) endi = n;
    int s = 0;
    for (int i = beg; i < endi; ++i) s += deg[i];
    sums[t] = s;
    __syncthreads();
    for (int off = 1; off < 1024; off <<= 1) {
        int v = (t >= off) ? sums[t - off] : 0;
        __syncthreads();
        sums[t] += v;
        __syncthreads();
    }
    int run = (t == 0) ? 0 : sums[t - 1];
    for (int i = beg; i < endi; ++i) {
        rowptr[i] = run;
        cursor[i] = run;
        run += deg[i];
    }
    if (t == 0) rowptr[n] = sums[1023];
}

__global__ void fill_kernel(const int* __restrict__ src, const int* __restrict__ tgt,
                            const float* __restrict__ ew, int* __restrict__ cursor,
                            int2* __restrict__ esw, int e) {
    int i = blockIdx.x * blockDim.x + threadIdx.x;
    if (i < e) {
        int p = atomicAdd(&cursor[tgt[i]], 1);
        esw[p] = make_int2(src[i], __float_as_int(ew[i]));
    }
}

// ---------------------------------------------------------------------------
// Conversion kernels
// ---------------------------------------------------------------------------
__global__ void convert_x_kernel(const float* __restrict__ in,
                                 __nv_bfloat16* __restrict__ hi,
                                 __nv_bfloat16* __restrict__ lo, int n4) {
    int i = blockIdx.x * blockDim.x + threadIdx.x;
    if (i >= n4) return;
    float4 v = ((const float4*)in)[i];
    __nv_bfloat16 h0, h1, h2, h3, l0, l1, l2, l3;
    split2(v.x, h0, l0); split2(v.y, h1, l1);
    split2(v.z, h2, l2); split2(v.w, h3, l3);
    uint2 uh, ul;
    uh.x = pack_bf(h0, h1); uh.y = pack_bf(h2, h3);
    ul.x = pack_bf(l0, l1); ul.y = pack_bf(l2, l3);
    *(uint2*)&hi[(size_t)i * 4] = uh;
    *(uint2*)&lo[(size_t)i * 4] = ul;
}

// Transpose + split + pad: W[K][N] -> Wt{hi,lo}[Npad][K]
__global__ void convert_w_kernel(const float* __restrict__ W, int K, int N, int Npad,
                                 __nv_bfloat16* __restrict__ oh,
                                 __nv_bfloat16* __restrict__ ol) {
    int idx = blockIdx.x * blockDim.x + threadIdx.x;
    if (idx >= Npad * K) return;
    int n = idx / K, k = idx % K;
    float v = (n < N) ? W[(size_t)k * N + n] : 0.0f;
    __nv_bfloat16 h, l;
    split2(v, h, l);
    oh[idx] = h; ol[idx] = l;
}

// ---------------------------------------------------------------------------
// Tensor-core GEMM: C[M,NOUT] = A[M,K] @ W[K,N] + bias, via 3-term bf16 split.
// A given as (Ah, Al) bf16 [M][K]; W given transposed (Wh, Wl) bf16 [BN][K].
// BM=128, BK=32, 256 threads (8 warps).
// ---------------------------------------------------------------------------
template<int K, int NOUT, int BN>
__global__ void __launch_bounds__(256, 1)
gemm_mma_kernel(const __nv_bfloat16* __restrict__ Ah,
                const __nv_bfloat16* __restrict__ Al,
                const __nv_bfloat16* __restrict__ Wh,
                const __nv_bfloat16* __restrict__ Wl,
                const float* __restrict__ bias,
                float* __restrict__ C, int M) {
    constexpr int BM  = 128, BK = 32;
    constexpr int BKP = BK + 8;                 // 80B row stride: 16B-aligned, LDSM conflict-free
    constexpr int WARPS_N = BN / 32;            // 4 or 2
    constexpr int WARPS_M = 8 / WARPS_N;        // 2 or 4
    constexpr int MT = (BM / WARPS_M) / 16;     // m16 tiles per warp: 4 or 2
    constexpr int NT = 4;                       // n8 tiles per warp (32 wide)

    __shared__ __nv_bfloat16 sAh[BM][BKP];
    __shared__ __nv_bfloat16 sAl[BM][BKP];
    __shared__ __nv_bfloat16 sWh[BN][BKP];
    __shared__ __nv_bfloat16 sWl[BN][BKP];

    const int tid  = threadIdx.x;
    const int wid  = tid >> 5;
    const int lane = tid & 31;
    const int row0 = blockIdx.x * BM;
    const int wm   = (wid / WARPS_N) * (MT * 16);
    const int wn   = (wid % WARPS_N) * 32;

    float acc[MT][NT][4];
#pragma unroll
    for (int i = 0; i < MT; ++i)
#pragma unroll
        for (int j = 0; j < NT; ++j)
#pragma unroll
            for (int q = 0; q < 4; ++q) acc[i][j][q] = 0.0f;

    for (int kk = 0; kk < K; kk += BK) {
        // ---- A tiles (hi & lo), 16B chunks ----
#pragma unroll
        for (int t = tid; t < BM * 4; t += 256) {
            int r = t >> 2, c = (t & 3) * 8;
            int grow = row0 + r;
            uint4 vh = make_uint4(0, 0, 0, 0), vl = make_uint4(0, 0, 0, 0);
            if (grow < M) {
                vh = *(const uint4*)&Ah[(size_t)grow * K + kk + c];
                vl = *(const uint4*)&Al[(size_t)grow * K + kk + c];
            }
            *(uint4*)&sAh[r][c] = vh;
            *(uint4*)&sAl[r][c] = vl;
        }
        // ---- W tiles (pre-padded; no guard) ----
#pragma unroll
        for (int t = tid; t < BN * 4; t += 256) {
            int r = t >> 2, c = (t & 3) * 8;
            *(uint4*)&sWh[r][c] = *(const uint4*)&Wh[(size_t)r * K + kk + c];
            *(uint4*)&sWl[r][c] = *(const uint4*)&Wl[(size_t)r * K + kk + c];
        }
        __syncthreads();

#pragma unroll
        for (int ks = 0; ks < BK; ks += 16) {
            uint32_t ah[MT][4], al[MT][4];
#pragma unroll
            for (int mt = 0; mt < MT; ++mt) {
                int r = wm + mt * 16 + (lane & 15);
                int c = ks + ((lane >> 4) << 3);
                ldsm4(ah[mt], &sAh[r][c]);
                ldsm4(al[mt], &sAl[r][c]);
            }
            uint32_t bh[NT][2], bl[NT][2];
#pragma unroll
            for (int np = 0; np < NT / 2; ++np) {
                int n = wn + np * 16 + (lane & 7) + ((lane >> 4) << 3);
                int c = ks + (((lane >> 3) & 1) << 3);
                uint32_t t4[4];
                ldsm4(t4, &sWh[n][c]);
                bh[2 * np][0] = t4[0]; bh[2 * np][1] = t4[1];
                bh[2 * np + 1][0] = t4[2]; bh[2 * np + 1][1] = t4[3];
                ldsm4(t4, &sWl[n][c]);
                bl[2 * np][0] = t4[0]; bl[2 * np][1] = t4[1];
                bl[2 * np + 1][0] = t4[2]; bl[2 * np + 1][1] = t4[3];
            }
#pragma unroll
            for (int mt = 0; mt < MT; ++mt)
#pragma unroll
                for (int nt = 0; nt < NT; ++nt) {
                    mma_bf16(acc[mt][nt], ah[mt], bh[nt]);   // hi*hi
                    mma_bf16(acc[mt][nt], ah[mt], bl[nt]);   // hi*lo
                    mma_bf16(acc[mt][nt], al[mt], bh[nt]);   // lo*hi
                }
        }
        __syncthreads();
    }

    // ---- epilogue: bias + store fp32 ----
    const int rbase = lane >> 2;          // 0..7
    const int cbase = (lane & 3) * 2;
#pragma unroll
    for (int mt = 0; mt < MT; ++mt)
#pragma unroll
        for (int nt = 0; nt < NT; ++nt) {
            int col = wn + nt * 8 + cbase;
            if (col >= NOUT) continue;
            float bx = bias[col], by = bias[col + 1];
#pragma unroll
            for (int h = 0; h < 2; ++h) {
                int row = row0 + wm + mt * 16 + rbase + h * 8;
                if (row < M) {
                    float2 v;
                    v.x = acc[mt][nt][h * 2 + 0] + bx;
                    v.y = acc[mt][nt][h * 2 + 1] + by;
                    *(float2*)&C[(size_t)row * NOUT + col] = v;
                }
            }
        }
}

// ---------------------------------------------------------------------------
// Aggregation (gather-CSR), F=128, warp per node, float4 per lane, 4x MLP.
// Outputs: optional fp32 (outF) and bf16 hi/lo split pair (outH/outL).
// MODE 0: relu(sum);  MODE 1: relu(sum) + res
// ---------------------------------------------------------------------------
template<int MODE>
__global__ void agg128_kernel(const float* __restrict__ h,
                              const int* __restrict__ rowptr,
                              const int2* __restrict__ esw,
                              const float* __restrict__ res,
                              float* __restrict__ outF,
                              __nv_bfloat16* __restrict__ outH,
                              __nv_bfloat16* __restrict__ outL, int n) {
    int warp = (blockIdx.x * blockDim.x + threadIdx.x) >> 5;
    int lane = threadIdx.x & 31;
    if (warp >= n) return;
    int beg = rowptr[warp];
    int end = rowptr[warp + 1];

    const float4* h4 = (const float4*)h;
    float4 acc = make_float4(0.f, 0.f, 0.f, 0.f);

    int j = beg;
    for (; j + 3 < end; j += 4) {
        int2 sw0 = __ldg(&esw[j]);
        int2 sw1 = __ldg(&esw[j + 1]);
        int2 sw2 = __ldg(&esw[j + 2]);
        int2 sw3 = __ldg(&esw[j + 3]);
        float w0 = __int_as_float(sw0.y);
        float w1 = __int_as_float(sw1.y);
        float w2 = __int_as_float(sw2.y);
        float w3 = __int_as_float(sw3.y);
        float4 v0 = __ldg(&h4[(size_t)sw0.x * 32 + lane]);
        float4 v1 = __ldg(&h4[(size_t)sw1.x * 32 + lane]);
        float4 v2 = __ldg(&h4[(size_t)sw2.x * 32 + lane]);
        float4 v3 = __ldg(&h4[(size_t)sw3.x * 32 + lane]);
        acc.x = fmaf(v0.x, w0, acc.x); acc.y = fmaf(v0.y, w0, acc.y);
        acc.z = fmaf(v0.z, w0, acc.z); acc.w = fmaf(v0.w, w0, acc.w);
        acc.x = fmaf(v1.x, w1, acc.x); acc.y = fmaf(v1.y, w1, acc.y);
        acc.z = fmaf(v1.z, w1, acc.z); acc.w = fmaf(v1.w, w1, acc.w);
        acc.x = fmaf(v2.x, w2, acc.x); acc.y = fmaf(v2.y, w2, acc.y);
        acc.z = fmaf(v2.z, w2, acc.z); acc.w = fmaf(v2.w, w2, acc.w);
        acc.x = fmaf(v3.x, w3, acc.x); acc.y = fmaf(v3.y, w3, acc.y);
        acc.z = fmaf(v3.z, w3, acc.z); acc.w = fmaf(v3.w, w3, acc.w);
    }
    for (; j < end; ++j) {
        int2 sw = __ldg(&esw[j]);
        float w = __int_as_float(sw.y);
        float4 v = __ldg(&h4[(size_t)sw.x * 32 + lane]);
        acc.x = fmaf(v.x, w, acc.x); acc.y = fmaf(v.y, w, acc.y);
        acc.z = fmaf(v.z, w, acc.z); acc.w = fmaf(v.w, w, acc.w);
    }

    acc.x = fmaxf(acc.x, 0.f); acc.y = fmaxf(acc.y, 0.f);
    acc.z = fmaxf(acc.z, 0.f); acc.w = fmaxf(acc.w, 0.f);
    if (MODE == 1) {
        float4 r = ((const float4*)res)[(size_t)warp * 32 + lane];
        acc.x += r.x; acc.y += r.y; acc.z += r.z; acc.w += r.w;
    }
    if (outF)
        ((float4*)outF)[(size_t)warp * 32 + lane] = acc;

    __nv_bfloat16 h0, h1, h2, h3, l0, l1, l2, l3;
    split2(acc.x, h0, l0); split2(acc.y, h1, l1);
    split2(acc.z, h2, l2); split2(acc.w, h3, l3);
    uint2 uh, ul;
    uh.x = pack_bf(h0, h1); uh.y = pack_bf(h2, h3);
    ul.x = pack_bf(l0, l1); ul.y = pack_bf(l2, l3);
    *(uint2*)&outH[(size_t)warp * 128 + lane * 4] = uh;
    *(uint2*)&outL[(size_t)warp * 128 + lane * 4] = ul;
}

// ---------------------------------------------------------------------------
// Final aggregation (F=40) fused with log_softmax; writes d_out directly.
// ---------------------------------------------------------------------------
__global__ void agg40_lsm_kernel(const float* __restrict__ h,
                                 const int* __restrict__ rowptr,
                                 const int2* __restrict__ esw,
                                 float* __restrict__ out, int n) {
    int warp = (blockIdx.x * blockDim.x + threadIdx.x) >> 5;
    int lane = threadIdx.x & 31;
    if (warp >= n) return;
    int beg = rowptr[warp];
    int end = rowptr[warp + 1];

    float a0 = 0.f, a1 = 0.f;
    for (int j = beg; j < end; ++j) {
        int2 sw = __ldg(&esw[j]);
        float w = __int_as_float(sw.y);
        const float* hp = h + (size_t)sw.x * F_OUT;
        a0 = fmaf(__ldg(&hp[lane]), w, a0);
        if (lane < 8) a1 = fmaf(__ldg(&hp[32 + lane]), w, a1);
    }

    float m = a0;
    if (lane < 8) m = fmaxf(m, a1);
#pragma unroll
    for (int o = 16; o > 0; o >>= 1)
        m = fmaxf(m, __shfl_xor_sync(0xffffffffu, m, o));

    float s = expf(a0 - m) + ((lane < 8) ? expf(a1 - m) : 0.f);
#pragma unroll
    for (int o = 16; o > 0; o >>= 1)
        s += __shfl_xor_sync(0xffffffffu, s, o);
    float lse = logf(s);

    out[(size_t)warp * F_OUT + lane] = a0 - m - lse;
    if (lane < 8)
        out[(size_t)warp * F_OUT + 32 + lane] = a1 - m - lse;
}

// ---------------------------------------------------------------------------
// Launch
// ---------------------------------------------------------------------------
extern "C" void kernel_launch(void* const* d_in, const int* in_sizes, int n_in,
                              void* d_out, int out_size) {
    const float* x   = (const float*)d_in[0];
    const int*   src = (const int*)  d_in[1];
    const int*   tgt = (const int*)  d_in[2];
    const float* ew  = (const float*)d_in[3];
    const float* W0  = (const float*)d_in[4];
    const float* b0  = (const float*)d_in[5];
    const float* W1  = (const float*)d_in[6];
    const float* b1  = (const float*)d_in[7];
    const float* W2  = (const float*)d_in[8];
    const float* b2  = (const float*)d_in[9];
    const float* W3  = (const float*)d_in[10];
    const float* b3  = (const float*)d_in[11];
    float* out = (float*)d_out;

    float *h, *x0;
    __nv_bfloat16 *xh, *xl, *p0h, *p0l, *p1h, *p1l;
    __nv_bfloat16 *w0h, *w0l, *w1h, *w1l, *w2h, *w2l, *w3h, *w3l;
    int *deg, *rowptr, *cursor;
    int2* esw;
    cudaGetSymbolAddress((void**)&h,   g_h);
    cudaGetSymbolAddress((void**)&x0,  g_x0);
    cudaGetSymbolAddress((void**)&xh,  g_xh);
    cudaGetSymbolAddress((void**)&xl,  g_xl);
    cudaGetSymbolAddress((void**)&p0h, g_p0h);
    cudaGetSymbolAddress((void**)&p0l, g_p0l);
    cudaGetSymbolAddress((void**)&p1h, g_p1h);
    cudaGetSymbolAddress((void**)&p1l, g_p1l);
    cudaGetSymbolAddress((void**)&w0h, g_w0h);
    cudaGetSymbolAddress((void**)&w0l, g_w0l);
    cudaGetSymbolAddress((void**)&w1h, g_w1h);
    cudaGetSymbolAddress((void**)&w1l, g_w1l);
    cudaGetSymbolAddress((void**)&w2h, g_w2h);
    cudaGetSymbolAddress((void**)&w2l, g_w2l);
    cudaGetSymbolAddress((void**)&w3h, g_w3h);
    cudaGetSymbolAddress((void**)&w3l, g_w3l);
    cudaGetSymbolAddress((void**)&deg,    g_deg);
    cudaGetSymbolAddress((void**)&rowptr, g_rowptr);
    cudaGetSymbolAddress((void**)&cursor, g_cursor);
    cudaGetSymbolAddress((void**)&esw,    g_esw);

    const int M = NNODES;
    const int E = NEDGES;

    // ---- CSR build (by target) ----
    zero_int_kernel<<<(M + 255) / 256, 256>>>(deg, M);
    hist_kernel<<<(E + 255) / 256, 256>>>(tgt, deg, E);
    scan_kernel<<<1, 1024>>>(deg, rowptr, cursor, M);
    fill_kernel<<<(E + 255) / 256, 256>>>(src, tgt, ew, cursor, esw, E);

    // ---- conversions ----
    {
        int n4 = M * F_IN / 4;
        convert_x_kernel<<<(n4 + 255) / 256, 256>>>(x, xh, xl, n4);
        convert_w_kernel<<<(128 * 256 + 255) / 256, 256>>>(W0, 256, 128, 128, w0h, w0l);
        convert_w_kernel<<<(128 * 128 + 255) / 256, 256>>>(W1, 128, 128, 128, w1h, w1l);
        convert_w_kernel<<<(128 * 128 + 255) / 256, 256>>>(W2, 128, 128, 128, w2h, w2l);
        convert_w_kernel<<<( 64 * 128 + 255) / 256, 256>>>(W3, 128,  40,  64, w3h, w3l);
    }

    const int gemm_blocks = (M + 127) / 128;
    const int agg_blocks  = (M + 7) / 8;

    // ---- layer 0: x0 = relu(agg(x @ W0 + b0)); keep fp32 + split pair ----
    gemm_mma_kernel<F_IN, F_HID, 128><<<gemm_blocks, 256>>>(xh, xl, w0h, w0l, b0, h, M);
    agg128_kernel<0><<<agg_blocks, 256>>>(h, rowptr, esw, nullptr, x0, p0h, p0l, M);

    // ---- layer 1: x1 = relu(agg(x0 @ W1 + b1)); split pair only ----
    gemm_mma_kernel<F_HID, F_HID, 128><<<gemm_blocks, 256>>>(p0h, p0l, w1h, w1l, b1, h, M);
    agg128_kernel<0><<<agg_blocks, 256>>>(h, rowptr, esw, nullptr, nullptr, p1h, p1l, M);

    // ---- layer 2: x2 = relu(agg(x1 @ W2 + b2)) + x0; split pair only ----
    gemm_mma_kernel<F_HID, F_HID, 128><<<gemm_blocks, 256>>>(p1h, p1l, w2h, w2l, b2, h, M);
    agg128_kernel<1><<<agg_blocks, 256>>>(h, rowptr, esw, x0, nullptr, p0h, p0l, M);

    // ---- layer 3: out = log_softmax(agg(x2 @ W3 + b3)) ----
    gemm_mma_kernel<F_HID, F_OUT, 64><<<gemm_blocks, 256>>>(p0h, p0l, w3h, w3l, b3, h, M);
    agg40_lsm_kernel<<<agg_blocks, 256>>>(h, rowptr, esw, out, M);
}

// round 11
// speedup vs baseline: 1.3435x; 1.1114x over previous
#include <cuda_runtime.h>
#include <cuda_bf16.h>
#include <math.h>
#include <stdint.h>

// Problem constants (fixed by the reference setup).
#define NNODES 100000
#define NEDGES 1600000
#define F_IN   256
#define F_HID  128
#define F_OUT  40

// ---------------------------------------------------------------------------
// Scratch (device globals; no cudaMalloc allowed)
// ---------------------------------------------------------------------------
__device__ float         g_h  [NNODES * F_HID];
__device__ float         g_x0 [NNODES * F_HID];
__device__ __nv_bfloat16 g_xh [NNODES * F_IN];
__device__ __nv_bfloat16 g_xl [NNODES * F_IN];
__device__ __nv_bfloat16 g_p0h[NNODES * F_HID];
__device__ __nv_bfloat16 g_p0l[NNODES * F_HID];
__device__ __nv_bfloat16 g_p1h[NNODES * F_HID];
__device__ __nv_bfloat16 g_p1l[NNODES * F_HID];
__device__ __nv_bfloat16 g_w0h[128 * 256], g_w0l[128 * 256];
__device__ __nv_bfloat16 g_w1h[128 * 128], g_w1l[128 * 128];
__device__ __nv_bfloat16 g_w2h[128 * 128], g_w2l[128 * 128];
__device__ __nv_bfloat16 g_w3h[ 64 * 128], g_w3l[ 64 * 128];
__device__ int  g_deg   [NNODES];
__device__ int  g_rowptr[NNODES + 1];
__device__ int  g_cursor[NNODES];
__device__ int2 g_esw   [NEDGES];

// ---------------------------------------------------------------------------
// Helpers
// ---------------------------------------------------------------------------
__device__ __forceinline__ void split2(float v, __nv_bfloat16& h, __nv_bfloat16& l) {
    h = __float2bfloat16(v);
    l = __float2bfloat16(v - __bfloat162float(h));
}

__device__ __forceinline__ uint32_t pack_bf(__nv_bfloat16 a, __nv_bfloat16 b) {
    return ((uint32_t)__bfloat16_as_ushort(b) << 16) | (uint32_t)__bfloat16_as_ushort(a);
}

__device__ __forceinline__ void ldsm4(uint32_t* d, const void* p) {
    uint32_t a = (uint32_t)__cvta_generic_to_shared(p);
    asm volatile("ldmatrix.sync.aligned.m8n8.x4.shared.b16 {%0,%1,%2,%3}, [%4];\n"
                 : "=r"(d[0]), "=r"(d[1]), "=r"(d[2]), "=r"(d[3]) : "r"(a));
}

__device__ __forceinline__ void mma_bf16(float* c, const uint32_t* a, const uint32_t* b) {
    asm volatile(
        "mma.sync.aligned.m16n8k16.row.col.f32.bf16.bf16.f32 "
        "{%0,%1,%2,%3}, {%4,%5,%6,%7}, {%8,%9}, {%0,%1,%2,%3};\n"
        : "+f"(c[0]), "+f"(c[1]), "+f"(c[2]), "+f"(c[3])
        : "r"(a[0]), "r"(a[1]), "r"(a[2]), "r"(a[3]), "r"(b[0]), "r"(b[1]));
}

// cp.async 16B with zero-fill when src_bytes == 0
__device__ __forceinline__ void cpa16(void* dst_smem, const void* src, int src_bytes) {
    uint32_t d = (uint32_t)__cvta_generic_to_shared(dst_smem);
    asm volatile("cp.async.cg.shared.global [%0], [%1], 16, %2;\n"
                 :: "r"(d), "l"(src), "r"(src_bytes));
}
__device__ __forceinline__ void cpa_commit() {
    asm volatile("cp.async.commit_group;\n");
}
template<int N>
__device__ __forceinline__ void cpa_wait() {
    asm volatile("cp.async.wait_group %0;\n" :: "n"(N));
}

// ---------------------------------------------------------------------------
// CSR build
// ---------------------------------------------------------------------------
__global__ void zero_int_kernel(int* p, int n) {
    int i = blockIdx.x * blockDim.x + threadIdx.x;
    if (i < n) p[i] = 0;
}

__global__ void hist_kernel(const int* __restrict__ tgt, int* __restrict__ deg, int e) {
    int i = blockIdx.x * blockDim.x + threadIdx.x;
    if (i < e) atomicAdd(&deg[tgt[i]], 1);
}

__global__ void scan_kernel(const int* __restrict__ deg, int* __restrict__ rowptr,
                            int* __restrict__ cursor, int n) {
    __shared__ int sums[1024];
    int t = threadIdx.x;
    const int CH = (n + 1023) >> 10;
    int beg = t * CH;
    int endi = beg + CH; if (endi > n) endi = n;
    int s = 0;
    for (int i = beg; i < endi; ++i) s += deg[i];
    sums[t] = s;
    __syncthreads();
    for (int off = 1; off < 1024; off <<= 1) {
        int v = (t >= off) ? sums[t - off] : 0;
        __syncthreads();
        sums[t] += v;
        __syncthreads();
    }
    int run = (t == 0) ? 0 : sums[t - 1];
    for (int i = beg; i < endi; ++i) {
        rowptr[i] = run;
        cursor[i] = run;
        run += deg[i];
    }
    if (t == 0) rowptr[n] = sums[1023];
}

__global__ void fill_kernel(const int* __restrict__ src, const int* __restrict__ tgt,
                            const float* __restrict__ ew, int* __restrict__ cursor,
                            int2* __restrict__ esw, int e) {
    int i = blockIdx.x * blockDim.x + threadIdx.x;
    if (i < e) {
        int p = atomicAdd(&cursor[tgt[i]], 1);
        esw[p] = make_int2(src[i], __float_as_int(ew[i]));
    }
}

// ---------------------------------------------------------------------------
// Conversion kernels
// ---------------------------------------------------------------------------
__global__ void convert_x_kernel(const float* __restrict__ in,
                                 __nv_bfloat16* __restrict__ hi,
                                 __nv_bfloat16* __restrict__ lo, int n4) {
    int i = blockIdx.x * blockDim.x + threadIdx.x;
    if (i >= n4) return;
    float4 v = ((const float4*)in)[i];
    __nv_bfloat16 h0, h1, h2, h3, l0, l1, l2, l3;
    split2(v.x, h0, l0); split2(v.y, h1, l1);
    split2(v.z, h2, l2); split2(v.w, h3, l3);
    uint2 uh, ul;
    uh.x = pack_bf(h0, h1); uh.y = pack_bf(h2, h3);
    ul.x = pack_bf(l0, l1); ul.y = pack_bf(l2, l3);
    *(uint2*)&hi[(size_t)i * 4] = uh;
    *(uint2*)&lo[(size_t)i * 4] = ul;
}

__global__ void convert_w_kernel(const float* __restrict__ W, int K, int N, int Npad,
                                 __nv_bfloat16* __restrict__ oh,
                                 __nv_bfloat16* __restrict__ ol) {
    int idx = blockIdx.x * blockDim.x + threadIdx.x;
    if (idx >= Npad * K) return;
    int n = idx / K, k = idx % K;
    float v = (n < N) ? W[(size_t)k * N + n] : 0.0f;
    __nv_bfloat16 h, l;
    split2(v, h, l);
    oh[idx] = h; ol[idx] = l;
}

// ---------------------------------------------------------------------------
// Tensor-core GEMM (cp.async 2-stage pipelined).
// C[M,NOUT] = A[M,K] @ W[K,N] + bias via 3-term bf16 split.
// A as (Ah, Al) bf16 [M][K]; W transposed (Wh, Wl) bf16 [BN][K].
// BM=128, BK=32, 256 threads (8 warps). Dynamic smem, 2 stages.
// ---------------------------------------------------------------------------
template<int K, int NOUT, int BN>
__global__ void __launch_bounds__(256)
gemm_mma_kernel(const __nv_bfloat16* __restrict__ Ah,
                const __nv_bfloat16* __restrict__ Al,
                const __nv_bfloat16* __restrict__ Wh,
                const __nv_bfloat16* __restrict__ Wl,
                const float* __restrict__ bias,
                float* __restrict__ C, int M) {
    constexpr int BM  = 128, BK = 32;
    constexpr int BKP = BK + 8;                 // 80B rows: 16B-aligned, LDSM conflict-free
    constexpr int WARPS_N = BN / 32;            // 4 or 2
    constexpr int WARPS_M = 8 / WARPS_N;        // 2 or 4
    constexpr int MT = (BM / WARPS_M) / 16;     // 4 or 2
    constexpr int NT = 4;
    constexpr int TA = BM * BKP;                // elements per A tile
    constexpr int TW = BN * BKP;
    constexpr int STAGE = 2 * TA + 2 * TW;      // Ah, Al, Wh, Wl
    constexpr int NKI = K / BK;

    extern __shared__ __align__(16) __nv_bfloat16 sm[];

    const int tid  = threadIdx.x;
    const int wid  = tid >> 5;
    const int lane = tid & 31;
    const int row0 = blockIdx.x * BM;
    const int wm   = (wid / WARPS_N) * (MT * 16);
    const int wn   = (wid % WARPS_N) * 32;

    float acc[MT][NT][4];
#pragma unroll
    for (int i = 0; i < MT; ++i)
#pragma unroll
        for (int j = 0; j < NT; ++j)
#pragma unroll
            for (int q = 0; q < 4; ++q) acc[i][j][q] = 0.0f;

    // ---- async stage loader ----
    auto load_stage = [&](int s, int kk) {
        __nv_bfloat16* bAh = sm + s * STAGE;
        __nv_bfloat16* bAl = bAh + TA;
        __nv_bfloat16* bWh = bAl + TA;
        __nv_bfloat16* bWl = bWh + TW;
        // A: BM rows x 32 cols, 16B (8 elem) chunks -> BM*4 chunks per tile
#pragma unroll
        for (int t = tid; t < BM * 4; t += 256) {
            int r = t >> 2, c = (t & 3) * 8;
            int grow = row0 + r;
            size_t ridx = (grow < M) ? (size_t)grow : 0;
            int nb = (grow < M) ? 16 : 0;
            cpa16(&bAh[r * BKP + c], &Ah[ridx * K + kk + c], nb);
            cpa16(&bAl[r * BKP + c], &Al[ridx * K + kk + c], nb);
        }
        // W: BN rows (pre-padded; no guard)
#pragma unroll
        for (int t = tid; t < BN * 4; t += 256) {
            int r = t >> 2, c = (t & 3) * 8;
            cpa16(&bWh[r * BKP + c], &Wh[(size_t)r * K + kk + c], 16);
            cpa16(&bWl[r * BKP + c], &Wl[(size_t)r * K + kk + c], 16);
        }
    };

    load_stage(0, 0);
    cpa_commit();

    for (int it = 0; it < NKI; ++it) {
        if (it + 1 < NKI) load_stage((it + 1) & 1, (it + 1) * BK);
        cpa_commit();
        cpa_wait<1>();          // stage `it` resident; stage `it+1` in flight
        __syncthreads();

        const __nv_bfloat16* bAh = sm + (it & 1) * STAGE;
        const __nv_bfloat16* bAl = bAh + TA;
        const __nv_bfloat16* bWh = bAl + TA;
        const __nv_bfloat16* bWl = bWh + TW;

#pragma unroll
        for (int ks = 0; ks < BK; ks += 16) {
            uint32_t ah[MT][4], al[MT][4];
#pragma unroll
            for (int mt = 0; mt < MT; ++mt) {
                int r = wm + mt * 16 + (lane & 15);
                int c = ks + ((lane >> 4) << 3);
                ldsm4(ah[mt], &bAh[r * BKP + c]);
                ldsm4(al[mt], &bAl[r * BKP + c]);
            }
            uint32_t bh[NT][2], bl[NT][2];
#pragma unroll
            for (int np = 0; np < NT / 2; ++np) {
                int n = wn + np * 16 + (lane & 7) + ((lane >> 4) << 3);
                int c = ks + (((lane >> 3) & 1) << 3);
                uint32_t t4[4];
                ldsm4(t4, &bWh[n * BKP + c]);
                bh[2 * np][0] = t4[0]; bh[2 * np][1] = t4[1];
                bh[2 * np + 1][0] = t4[2]; bh[2 * np + 1][1] = t4[3];
                ldsm4(t4, &bWl[n * BKP + c]);
                bl[2 * np][0] = t4[0]; bl[2 * np][1] = t4[1];
                bl[2 * np + 1][0] = t4[2]; bl[2 * np + 1][1] = t4[3];
            }
#pragma unroll
            for (int mt = 0; mt < MT; ++mt)
#pragma unroll
                for (int nt = 0; nt < NT; ++nt) {
                    mma_bf16(acc[mt][nt], ah[mt], bh[nt]);   // hi*hi
                    mma_bf16(acc[mt][nt], ah[mt], bl[nt]);   // hi*lo
                    mma_bf16(acc[mt][nt], al[mt], bh[nt]);   // lo*hi
                }
        }
        __syncthreads();
    }

    // ---- epilogue: bias + store fp32 ----
    const int rbase = lane >> 2;
    const int cbase = (lane & 3) * 2;
#pragma unroll
    for (int mt = 0; mt < MT; ++mt)
#pragma unroll
        for (int nt = 0; nt < NT; ++nt) {
            int col = wn + nt * 8 + cbase;
            if (col >= NOUT) continue;
            float bx = bias[col], by = bias[col + 1];
#pragma unroll
            for (int h = 0; h < 2; ++h) {
                int row = row0 + wm + mt * 16 + rbase + h * 8;
                if (row < M) {
                    float2 v;
                    v.x = acc[mt][nt][h * 2 + 0] + bx;
                    v.y = acc[mt][nt][h * 2 + 1] + by;
                    *(float2*)&C[(size_t)row * NOUT + col] = v;
                }
            }
        }
}

// ---------------------------------------------------------------------------
// Aggregation (gather-CSR), F=128, warp per node, float4 per lane, 4x MLP.
// ---------------------------------------------------------------------------
template<int MODE>
__global__ void agg128_kernel(const float* __restrict__ h,
                              const int* __restrict__ rowptr,
                              const int2* __restrict__ esw,
                              const float* __restrict__ res,
                              float* __restrict__ outF,
                              __nv_bfloat16* __restrict__ outH,
                              __nv_bfloat16* __restrict__ outL, int n) {
    int warp = (blockIdx.x * blockDim.x + threadIdx.x) >> 5;
    int lane = threadIdx.x & 31;
    if (warp >= n) return;
    int beg = rowptr[warp];
    int end = rowptr[warp + 1];

    const float4* h4 = (const float4*)h;
    float4 acc = make_float4(0.f, 0.f, 0.f, 0.f);

    int j = beg;
    for (; j + 3 < end; j += 4) {
        int2 sw0 = __ldg(&esw[j]);
        int2 sw1 = __ldg(&esw[j + 1]);
        int2 sw2 = __ldg(&esw[j + 2]);
        int2 sw3 = __ldg(&esw[j + 3]);
        float w0 = __int_as_float(sw0.y);
        float w1 = __int_as_float(sw1.y);
        float w2 = __int_as_float(sw2.y);
        float w3 = __int_as_float(sw3.y);
        float4 v0 = __ldg(&h4[(size_t)sw0.x * 32 + lane]);
        float4 v1 = __ldg(&h4[(size_t)sw1.x * 32 + lane]);
        float4 v2 = __ldg(&h4[(size_t)sw2.x * 32 + lane]);
        float4 v3 = __ldg(&h4[(size_t)sw3.x * 32 + lane]);
        acc.x = fmaf(v0.x, w0, acc.x); acc.y = fmaf(v0.y, w0, acc.y);
        acc.z = fmaf(v0.z, w0, acc.z); acc.w = fmaf(v0.w, w0, acc.w);
        acc.x = fmaf(v1.x, w1, acc.x); acc.y = fmaf(v1.y, w1, acc.y);
        acc.z = fmaf(v1.z, w1, acc.z); acc.w = fmaf(v1.w, w1, acc.w);
        acc.x = fmaf(v2.x, w2, acc.x); acc.y = fmaf(v2.y, w2, acc.y);
        acc.z = fmaf(v2.z, w2, acc.z); acc.w = fmaf(v2.w, w2, acc.w);
        acc.x = fmaf(v3.x, w3, acc.x); acc.y = fmaf(v3.y, w3, acc.y);
        acc.z = fmaf(v3.z, w3, acc.z); acc.w = fmaf(v3.w, w3, acc.w);
    }
    for (; j < end; ++j) {
        int2 sw = __ldg(&esw[j]);
        float w = __int_as_float(sw.y);
        float4 v = __ldg(&h4[(size_t)sw.x * 32 + lane]);
        acc.x = fmaf(v.x, w, acc.x); acc.y = fmaf(v.y, w, acc.y);
        acc.z = fmaf(v.z, w, acc.z); acc.w = fmaf(v.w, w, acc.w);
    }

    acc.x = fmaxf(acc.x, 0.f); acc.y = fmaxf(acc.y, 0.f);
    acc.z = fmaxf(acc.z, 0.f); acc.w = fmaxf(acc.w, 0.f);
    if (MODE == 1) {
        float4 r = ((const float4*)res)[(size_t)warp * 32 + lane];
        acc.x += r.x; acc.y += r.y; acc.z += r.z; acc.w += r.w;
    }
    if (outF)
        ((float4*)outF)[(size_t)warp * 32 + lane] = acc;

    __nv_bfloat16 h0, h1, h2, h3, l0, l1, l2, l3;
    split2(acc.x, h0, l0); split2(acc.y, h1, l1);
    split2(acc.z, h2, l2); split2(acc.w, h3, l3);
    uint2 uh, ul;
    uh.x = pack_bf(h0, h1); uh.y = pack_bf(h2, h3);
    ul.x = pack_bf(l0, l1); ul.y = pack_bf(l2, l3);
    *(uint2*)&outH[(size_t)warp * 128 + lane * 4] = uh;
    *(uint2*)&outL[(size_t)warp * 128 + lane * 4] = ul;
}

// ---------------------------------------------------------------------------
// Final aggregation (F=40) fused with log_softmax; writes d_out directly.
// ---------------------------------------------------------------------------
__global__ void agg40_lsm_kernel(const float* __restrict__ h,
                                 const int* __restrict__ rowptr,
                                 const int2* __restrict__ esw,
                                 float* __restrict__ out, int n) {
    int warp = (blockIdx.x * blockDim.x + threadIdx.x) >> 5;
    int lane = threadIdx.x & 31;
    if (warp >= n) return;
    int beg = rowptr[warp];
    int end = rowptr[warp + 1];

    float a0 = 0.f, a1 = 0.f;
    for (int j = beg; j < end; ++j) {
        int2 sw = __ldg(&esw[j]);
        float w = __int_as_float(sw.y);
        const float* hp = h + (size_t)sw.x * F_OUT;
        a0 = fmaf(__ldg(&hp[lane]), w, a0);
        if (lane < 8) a1 = fmaf(__ldg(&hp[32 + lane]), w, a1);
    }

    float m = a0;
    if (lane < 8) m = fmaxf(m, a1);
#pragma unroll
    for (int o = 16; o > 0; o >>= 1)
        m = fmaxf(m, __shfl_xor_sync(0xffffffffu, m, o));

    float s = expf(a0 - m) + ((lane < 8) ? expf(a1 - m) : 0.f);
#pragma unroll
    for (int o = 16; o > 0; o >>= 1)
        s += __shfl_xor_sync(0xffffffffu, s, o);
    float lse = logf(s);

    out[(size_t)warp * F_OUT + lane] = a0 - m - lse;
    if (lane < 8)
        out[(size_t)warp * F_OUT + 32 + lane] = a1 - m - lse;
}

// ---------------------------------------------------------------------------
// Launch
// ---------------------------------------------------------------------------
extern "C" void kernel_launch(void* const* d_in, const int* in_sizes, int n_in,
                              void* d_out, int out_size) {
    const float* x   = (const float*)d_in[0];
    const int*   src = (const int*)  d_in[1];
    const int*   tgt = (const int*)  d_in[2];
    const float* ew  = (const float*)d_in[3];
    const float* W0  = (const float*)d_in[4];
    const float* b0  = (const float*)d_in[5];
    const float* W1  = (const float*)d_in[6];
    const float* b1  = (const float*)d_in[7];
    const float* W2  = (const float*)d_in[8];
    const float* b2  = (const float*)d_in[9];
    const float* W3  = (const float*)d_in[10];
    const float* b3  = (const float*)d_in[11];
    float* out = (float*)d_out;

    float *h, *x0;
    __nv_bfloat16 *xh, *xl, *p0h, *p0l, *p1h, *p1l;
    __nv_bfloat16 *w0h, *w0l, *w1h, *w1l, *w2h, *w2l, *w3h, *w3l;
    int *deg, *rowptr, *cursor;
    int2* esw;
    cudaGetSymbolAddress((void**)&h,   g_h);
    cudaGetSymbolAddress((void**)&x0,  g_x0);
    cudaGetSymbolAddress((void**)&xh,  g_xh);
    cudaGetSymbolAddress((void**)&xl,  g_xl);
    cudaGetSymbolAddress((void**)&p0h, g_p0h);
    cudaGetSymbolAddress((void**)&p0l, g_p0l);
    cudaGetSymbolAddress((void**)&p1h, g_p1h);
    cudaGetSymbolAddress((void**)&p1l, g_p1l);
    cudaGetSymbolAddress((void**)&w0h, g_w0h);
    cudaGetSymbolAddress((void**)&w0l, g_w0l);
    cudaGetSymbolAddress((void**)&w1h, g_w1h);
    cudaGetSymbolAddress((void**)&w1l, g_w1l);
    cudaGetSymbolAddress((void**)&w2h, g_w2h);
    cudaGetSymbolAddress((void**)&w2l, g_w2l);
    cudaGetSymbolAddress((void**)&w3h, g_w3h);
    cudaGetSymbolAddress((void**)&w3l, g_w3l);
    cudaGetSymbolAddress((void**)&deg,    g_deg);
    cudaGetSymbolAddress((void**)&rowptr, g_rowptr);
    cudaGetSymbolAddress((void**)&cursor, g_cursor);
    cudaGetSymbolAddress((void**)&esw,    g_esw);

    const int M = NNODES;
    const int E = NEDGES;

    // Dynamic smem sizes for the pipelined GEMMs (2 stages).
    // BN=128: 2*(2*128*40 + 2*128*40)*2B = 81920 B;  BN=64: 61440 B.
    const int SMEM_128 = 2 * (2 * 128 * 40 + 2 * 128 * 40) * 2;
    const int SMEM_64  = 2 * (2 * 128 * 40 + 2 *  64 * 40) * 2;
    cudaFuncSetAttribute(gemm_mma_kernel<F_IN,  F_HID, 128>,
                         cudaFuncAttributeMaxDynamicSharedMemorySize, SMEM_128);
    cudaFuncSetAttribute(gemm_mma_kernel<F_HID, F_HID, 128>,
                         cudaFuncAttributeMaxDynamicSharedMemorySize, SMEM_128);
    cudaFuncSetAttribute(gemm_mma_kernel<F_HID, F_OUT, 64>,
                         cudaFuncAttributeMaxDynamicSharedMemorySize, SMEM_64);

    // ---- CSR build (by target) ----
    zero_int_kernel<<<(M + 255) / 256, 256>>>(deg, M);
    hist_kernel<<<(E + 255) / 256, 256>>>(tgt, deg, E);
    scan_kernel<<<1, 1024>>>(deg, rowptr, cursor, M);
    fill_kernel<<<(E + 255) / 256, 256>>>(src, tgt, ew, cursor, esw, E);

    // ---- conversions ----
    {
        int n4 = M * F_IN / 4;
        convert_x_kernel<<<(n4 + 255) / 256, 256>>>(x, xh, xl, n4);
        convert_w_kernel<<<(128 * 256 + 255) / 256, 256>>>(W0, 256, 128, 128, w0h, w0l);
        convert_w_kernel<<<(128 * 128 + 255) / 256, 256>>>(W1, 128, 128, 128, w1h, w1l);
        convert_w_kernel<<<(128 * 128 + 255) / 256, 256>>>(W2, 128, 128, 128, w2h, w2l);
        convert_w_kernel<<<( 64 * 128 + 255) / 256, 256>>>(W3, 128,  40,  64, w3h, w3l);
    }

    const int gemm_blocks = (M + 127) / 128;
    const int agg_blocks  = (M + 7) / 8;

    // ---- layer 0 ----
    gemm_mma_kernel<F_IN, F_HID, 128><<<gemm_blocks, 256, SMEM_128>>>(xh, xl, w0h, w0l, b0, h, M);
    agg128_kernel<0><<<agg_blocks, 256>>>(h, rowptr, esw, nullptr, x0, p0h, p0l, M);

    // ---- layer 1 ----
    gemm_mma_kernel<F_HID, F_HID, 128><<<gemm_blocks, 256, SMEM_128>>>(p0h, p0l, w1h, w1l, b1, h, M);
    agg128_kernel<0><<<agg_blocks, 256>>>(h, rowptr, esw, nullptr, nullptr, p1h, p1l, M);

    // ---- layer 2 ----
    gemm_mma_kernel<F_HID, F_HID, 128><<<gemm_blocks, 256, SMEM_128>>>(p1h, p1l, w2h, w2l, b2, h, M);
    agg128_kernel<1><<<agg_blocks, 256>>>(h, rowptr, esw, x0, nullptr, p0h, p0l, M);

    // ---- layer 3 ----
    gemm_mma_kernel<F_HID, F_OUT, 64><<<gemm_blocks, 256, SMEM_64>>>(p0h, p0l, w3h, w3l, b3, h, M);
    agg40_lsm_kernel<<<agg_blocks, 256>>>(h, rowptr, esw, out, M);
}

// round 12
// speedup vs baseline: 1.3491x; 1.0041x over previous
#include <cuda_runtime.h>
#include <cuda_bf16.h>
#include <math.h>
#include <stdint.h>

// Problem constants (fixed by the reference setup).
#define NNODES 100000
#define NEDGES 1600000
#define F_IN   256
#define F_HID  128
#define F_OUT  40

// ---------------------------------------------------------------------------
// Scratch (device globals; no cudaMalloc allowed)
// ---------------------------------------------------------------------------
__device__ float         g_h  [NNODES * F_HID];
__device__ float         g_x0 [NNODES * F_HID];
__device__ __nv_bfloat16 g_xh [NNODES * F_IN];
__device__ __nv_bfloat16 g_xl [NNODES * F_IN];
__device__ __nv_bfloat16 g_p0h[NNODES * F_HID];
__device__ __nv_bfloat16 g_p0l[NNODES * F_HID];
__device__ __nv_bfloat16 g_p1h[NNODES * F_HID];
__device__ __nv_bfloat16 g_p1l[NNODES * F_HID];
__device__ __nv_bfloat16 g_w0h[128 * 256], g_w0l[128 * 256];
__device__ __nv_bfloat16 g_w1h[128 * 128], g_w1l[128 * 128];
__device__ __nv_bfloat16 g_w2h[128 * 128], g_w2l[128 * 128];
__device__ __nv_bfloat16 g_w3h[ 64 * 128], g_w3l[ 64 * 128];
__device__ int  g_deg   [NNODES];
__device__ int  g_rowptr[NNODES + 1];
__device__ int  g_cursor[NNODES];
__device__ int2 g_esw   [NEDGES];

// ---------------------------------------------------------------------------
// Helpers
// ---------------------------------------------------------------------------
__device__ __forceinline__ void split2(float v, __nv_bfloat16& h, __nv_bfloat16& l) {
    h = __float2bfloat16(v);
    l = __float2bfloat16(v - __bfloat162float(h));
}

__device__ __forceinline__ uint32_t pack_bf(__nv_bfloat16 a, __nv_bfloat16 b) {
    return ((uint32_t)__bfloat16_as_ushort(b) << 16) | (uint32_t)__bfloat16_as_ushort(a);
}

__device__ __forceinline__ void ldsm4(uint32_t* d, const void* p) {
    uint32_t a = (uint32_t)__cvta_generic_to_shared(p);
    asm volatile("ldmatrix.sync.aligned.m8n8.x4.shared.b16 {%0,%1,%2,%3}, [%4];\n"
                 : "=r"(d[0]), "=r"(d[1]), "=r"(d[2]), "=r"(d[3]) : "r"(a));
}

__device__ __forceinline__ void mma_bf16(float* c, const uint32_t* a, const uint32_t* b) {
    asm volatile(
        "mma.sync.aligned.m16n8k16.row.col.f32.bf16.bf16.f32 "
        "{%0,%1,%2,%3}, {%4,%5,%6,%7}, {%8,%9}, {%0,%1,%2,%3};\n"
        : "+f"(c[0]), "+f"(c[1]), "+f"(c[2]), "+f"(c[3])
        : "r"(a[0]), "r"(a[1]), "r"(a[2]), "r"(a[3]), "r"(b[0]), "r"(b[1]));
}

__device__ __forceinline__ void cpa16(void* dst_smem, const void* src, int src_bytes) {
    uint32_t d = (uint32_t)__cvta_generic_to_shared(dst_smem);
    asm volatile("cp.async.cg.shared.global [%0], [%1], 16, %2;\n"
                 :: "r"(d), "l"(src), "r"(src_bytes));
}
__device__ __forceinline__ void cpa_commit() {
    asm volatile("cp.async.commit_group;\n");
}
template<int N>
__device__ __forceinline__ void cpa_wait() {
    asm volatile("cp.async.wait_group %0;\n" :: "n"(N));
}

// ---------------------------------------------------------------------------
// CSR build
// ---------------------------------------------------------------------------
__global__ void zero_int_kernel(int* p, int n) {
    int i = blockIdx.x * blockDim.x + threadIdx.x;
    if (i < n) p[i] = 0;
}

__global__ void hist_kernel(const int* __restrict__ tgt, int* __restrict__ deg, int e) {
    int i = blockIdx.x * blockDim.x + threadIdx.x;
    if (i < e) atomicAdd(&deg[tgt[i]], 1);
}

__global__ void scan_kernel(const int* __restrict__ deg, int* __restrict__ rowptr,
                            int* __restrict__ cursor, int n) {
    __shared__ int sums[1024];
    int t = threadIdx.x;
    const int CH = (n + 1023) >> 10;
    int beg = t * CH;
    int endi = beg + CH; if (endi > n) endi = n;
    int s = 0;
    for (int i = beg; i < endi; ++i) s += deg[i];
    sums[t] = s;
    __syncthreads();
    for (int off = 1; off < 1024; off <<= 1) {
        int v = (t >= off) ? sums[t - off] : 0;
        __syncthreads();
        sums[t] += v;
        __syncthreads();
    }
    int run = (t == 0) ? 0 : sums[t - 1];
    for (int i = beg; i < endi; ++i) {
        rowptr[i] = run;
        cursor[i] = run;
        run += deg[i];
    }
    if (t == 0) rowptr[n] = sums[1023];
}

__global__ void fill_kernel(const int* __restrict__ src, const int* __restrict__ tgt,
                            const float* __restrict__ ew, int* __restrict__ cursor,
                            int2* __restrict__ esw, int e) {
    int i = blockIdx.x * blockDim.x + threadIdx.x;
    if (i < e) {
        int p = atomicAdd(&cursor[tgt[i]], 1);
        esw[p] = make_int2(src[i], __float_as_int(ew[i]));
    }
}

// ---------------------------------------------------------------------------
// Conversion kernels
// ---------------------------------------------------------------------------
__global__ void convert_x_kernel(const float* __restrict__ in,
                                 __nv_bfloat16* __restrict__ hi,
                                 __nv_bfloat16* __restrict__ lo, int n4) {
    int i = blockIdx.x * blockDim.x + threadIdx.x;
    if (i >= n4) return;
    float4 v = ((const float4*)in)[i];
    __nv_bfloat16 h0, h1, h2, h3, l0, l1, l2, l3;
    split2(v.x, h0, l0); split2(v.y, h1, l1);
    split2(v.z, h2, l2); split2(v.w, h3, l3);
    uint2 uh, ul;
    uh.x = pack_bf(h0, h1); uh.y = pack_bf(h2, h3);
    ul.x = pack_bf(l0, l1); ul.y = pack_bf(l2, l3);
    *(uint2*)&hi[(size_t)i * 4] = uh;
    *(uint2*)&lo[(size_t)i * 4] = ul;
}

// All four weights in one launch: transpose + split + pad.
// Segment s: W[K][N] -> Wt{hi,lo}[Npad][K]
__global__ void convert_w_all_kernel(const float* __restrict__ W0, __nv_bfloat16* oh0, __nv_bfloat16* ol0,
                                     const float* __restrict__ W1, __nv_bfloat16* oh1, __nv_bfloat16* ol1,
                                     const float* __restrict__ W2, __nv_bfloat16* oh2, __nv_bfloat16* ol2,
                                     const float* __restrict__ W3, __nv_bfloat16* oh3, __nv_bfloat16* ol3) {
    // sizes: s0: 128x256 (K=256,N=128), s1/s2: 128x128, s3: 64x128 (K=128,N=40,Npad=64)
    const int S0 = 128 * 256, S1 = 128 * 128, S2 = 128 * 128, S3 = 64 * 128;
    int idx = blockIdx.x * blockDim.x + threadIdx.x;
    const float* W; __nv_bfloat16 *oh, *ol; int K, N;
    if (idx < S0)                { W = W0; oh = oh0; ol = ol0; K = 256; N = 128; }
    else if ((idx -= S0) < S1)   { W = W1; oh = oh1; ol = ol1; K = 128; N = 128; }
    else if ((idx -= S1) < S2)   { W = W2; oh = oh2; ol = ol2; K = 128; N = 128; }
    else if ((idx -= S2) < S3)   { W = W3; oh = oh3; ol = ol3; K = 128; N = 40;  }
    else return;
    int n = idx / K, k = idx % K;
    float v = (n < N) ? W[(size_t)k * N + n] : 0.0f;
    __nv_bfloat16 h, l;
    split2(v, h, l);
    oh[idx] = h; ol[idx] = l;
}

// ---------------------------------------------------------------------------
// Persistent tensor-core GEMM (cp.async 2-stage pipelined, cross-tile prefetch).
// C[M,NOUT] = A[M,K] @ W[K,N] + bias via 3-term bf16 split.
// A as (Ah, Al) bf16 [M][K]; W transposed (Wh, Wl) bf16 [BN][K].
// BM=128, BK=32, 256 threads (8 warps). Grid = residency; blocks loop tiles.
// ---------------------------------------------------------------------------
template<int K, int NOUT, int BN>
__global__ void __launch_bounds__(256)
gemm_mma_kernel(const __nv_bfloat16* __restrict__ Ah,
                const __nv_bfloat16* __restrict__ Al,
                const __nv_bfloat16* __restrict__ Wh,
                const __nv_bfloat16* __restrict__ Wl,
                const float* __restrict__ bias,
                float* __restrict__ C, int M, int ntiles) {
    constexpr int BM  = 128, BK = 32;
    constexpr int BKP = BK + 8;
    constexpr int WARPS_N = BN / 32;
    constexpr int WARPS_M = 8 / WARPS_N;
    constexpr int MT = (BM / WARPS_M) / 16;
    constexpr int NT = 4;
    constexpr int TA = BM * BKP;
    constexpr int TW = BN * BKP;
    constexpr int STAGE = 2 * TA + 2 * TW;
    constexpr int NKI = K / BK;           // 8 (K=256) or 4 (K=128): even
    static_assert((NKI & 1) == 0, "NKI must be even for cross-tile parity");

    extern __shared__ __align__(16) __nv_bfloat16 sm[];

    const int tid  = threadIdx.x;
    const int wid  = tid >> 5;
    const int lane = tid & 31;
    const int wm   = (wid / WARPS_N) * (MT * 16);
    const int wn   = (wid % WARPS_N) * 32;

    // stage loader (async)
    auto load_stage = [&](int s, int row0, int kk) {
        __nv_bfloat16* bAh = sm + s * STAGE;
        __nv_bfloat16* bAl = bAh + TA;
        __nv_bfloat16* bWh = bAl + TA;
        __nv_bfloat16* bWl = bWh + TW;
#pragma unroll
        for (int t = tid; t < BM * 4; t += 256) {
            int r = t >> 2, c = (t & 3) * 8;
            int grow = row0 + r;
            size_t ridx = (grow < M) ? (size_t)grow : 0;
            int nb = (grow < M) ? 16 : 0;
            cpa16(&bAh[r * BKP + c], &Ah[ridx * K + kk + c], nb);
            cpa16(&bAl[r * BKP + c], &Al[ridx * K + kk + c], nb);
        }
#pragma unroll
        for (int t = tid; t < BN * 4; t += 256) {
            int r = t >> 2, c = (t & 3) * 8;
            cpa16(&bWh[r * BKP + c], &Wh[(size_t)r * K + kk + c], 16);
            cpa16(&bWl[r * BKP + c], &Wl[(size_t)r * K + kk + c], 16);
        }
    };

    int tile = blockIdx.x;
    if (tile >= ntiles) return;
    int row0 = tile * BM;

    load_stage(0, row0, 0);
    cpa_commit();

    const int rbase = lane >> 2;
    const int cbase = (lane & 3) * 2;

    while (true) {
        int next_tile = tile + gridDim.x;
        int next_row0 = next_tile * BM;

        float acc[MT][NT][4];
#pragma unroll
        for (int i = 0; i < MT; ++i)
#pragma unroll
            for (int j = 0; j < NT; ++j)
#pragma unroll
                for (int q = 0; q < 4; ++q) acc[i][j][q] = 0.0f;

        for (int it = 0; it < NKI; ++it) {
            // prefetch: next K-stage of this tile, or first stage of next tile
            if (it + 1 < NKI)
                load_stage((it + 1) & 1, row0, (it + 1) * BK);
            else if (next_tile < ntiles)
                load_stage(0, next_row0, 0);   // (NKI)&1 == 0: parity consistent
            cpa_commit();
            cpa_wait<1>();
            __syncthreads();

            const __nv_bfloat16* bAh = sm + (it & 1) * STAGE;
            const __nv_bfloat16* bAl = bAh + TA;
            const __nv_bfloat16* bWh = bAl + TA;
            const __nv_bfloat16* bWl = bWh + TW;

#pragma unroll
            for (int ks = 0; ks < BK; ks += 16) {
                uint32_t ah[MT][4], al[MT][4];
#pragma unroll
                for (int mt = 0; mt < MT; ++mt) {
                    int r = wm + mt * 16 + (lane & 15);
                    int c = ks + ((lane >> 4) << 3);
                    ldsm4(ah[mt], &bAh[r * BKP + c]);
                    ldsm4(al[mt], &bAl[r * BKP + c]);
                }
                uint32_t bh[NT][2], bl[NT][2];
#pragma unroll
                for (int np = 0; np < NT / 2; ++np) {
                    int n = wn + np * 16 + (lane & 7) + ((lane >> 4) << 3);
                    int c = ks + (((lane >> 3) & 1) << 3);
                    uint32_t t4[4];
                    ldsm4(t4, &bWh[n * BKP + c]);
                    bh[2 * np][0] = t4[0]; bh[2 * np][1] = t4[1];
                    bh[2 * np + 1][0] = t4[2]; bh[2 * np + 1][1] = t4[3];
                    ldsm4(t4, &bWl[n * BKP + c]);
                    bl[2 * np][0] = t4[0]; bl[2 * np][1] = t4[1];
                    bl[2 * np + 1][0] = t4[2]; bl[2 * np + 1][1] = t4[3];
                }
#pragma unroll
                for (int mt = 0; mt < MT; ++mt)
#pragma unroll
                    for (int nt = 0; nt < NT; ++nt) {
                        mma_bf16(acc[mt][nt], ah[mt], bh[nt]);
                        mma_bf16(acc[mt][nt], ah[mt], bl[nt]);
                        mma_bf16(acc[mt][nt], al[mt], bh[nt]);
                    }
            }
            __syncthreads();
        }

        // epilogue (registers only; overlaps the in-flight next-tile loads)
#pragma unroll
        for (int mt = 0; mt < MT; ++mt)
#pragma unroll
            for (int nt = 0; nt < NT; ++nt) {
                int col = wn + nt * 8 + cbase;
                if (col >= NOUT) continue;
                float bx = bias[col], by = bias[col + 1];
#pragma unroll
                for (int h = 0; h < 2; ++h) {
                    int row = row0 + wm + mt * 16 + rbase + h * 8;
                    if (row < M) {
                        float2 v;
                        v.x = acc[mt][nt][h * 2 + 0] + bx;
                        v.y = acc[mt][nt][h * 2 + 1] + by;
                        *(float2*)&C[(size_t)row * NOUT + col] = v;
                    }
                }
            }

        if (next_tile >= ntiles) break;
        tile = next_tile;
        row0 = next_row0;
    }
}

// ---------------------------------------------------------------------------
// Aggregation (gather-CSR), F=128, warp per node, float4 per lane, 4x MLP.
// ---------------------------------------------------------------------------
template<int MODE>
__global__ void agg128_kernel(const float* __restrict__ h,
                              const int* __restrict__ rowptr,
                              const int2* __restrict__ esw,
                              const float* __restrict__ res,
                              float* __restrict__ outF,
                              __nv_bfloat16* __restrict__ outH,
                              __nv_bfloat16* __restrict__ outL, int n) {
    int warp = (blockIdx.x * blockDim.x + threadIdx.x) >> 5;
    int lane = threadIdx.x & 31;
    if (warp >= n) return;
    int beg = rowptr[warp];
    int end = rowptr[warp + 1];

    const float4* h4 = (const float4*)h;
    float4 acc = make_float4(0.f, 0.f, 0.f, 0.f);

    int j = beg;
    for (; j + 3 < end; j += 4) {
        int2 sw0 = __ldg(&esw[j]);
        int2 sw1 = __ldg(&esw[j + 1]);
        int2 sw2 = __ldg(&esw[j + 2]);
        int2 sw3 = __ldg(&esw[j + 3]);
        float w0 = __int_as_float(sw0.y);
        float w1 = __int_as_float(sw1.y);
        float w2 = __int_as_float(sw2.y);
        float w3 = __int_as_float(sw3.y);
        float4 v0 = __ldg(&h4[(size_t)sw0.x * 32 + lane]);
        float4 v1 = __ldg(&h4[(size_t)sw1.x * 32 + lane]);
        float4 v2 = __ldg(&h4[(size_t)sw2.x * 32 + lane]);
        float4 v3 = __ldg(&h4[(size_t)sw3.x * 32 + lane]);
        acc.x = fmaf(v0.x, w0, acc.x); acc.y = fmaf(v0.y, w0, acc.y);
        acc.z = fmaf(v0.z, w0, acc.z); acc.w = fmaf(v0.w, w0, acc.w);
        acc.x = fmaf(v1.x, w1, acc.x); acc.y = fmaf(v1.y, w1, acc.y);
        acc.z = fmaf(v1.z, w1, acc.z); acc.w = fmaf(v1.w, w1, acc.w);
        acc.x = fmaf(v2.x, w2, acc.x); acc.y = fmaf(v2.y, w2, acc.y);
        acc.z = fmaf(v2.z, w2, acc.z); acc.w = fmaf(v2.w, w2, acc.w);
        acc.x = fmaf(v3.x, w3, acc.x); acc.y = fmaf(v3.y, w3, acc.y);
        acc.z = fmaf(v3.z, w3, acc.z); acc.w = fmaf(v3.w, w3, acc.w);
    }
    for (; j < end; ++j) {
        int2 sw = __ldg(&esw[j]);
        float w = __int_as_float(sw.y);
        float4 v = __ldg(&h4[(size_t)sw.x * 32 + lane]);
        acc.x = fmaf(v.x, w, acc.x); acc.y = fmaf(v.y, w, acc.y);
        acc.z = fmaf(v.z, w, acc.z); acc.w = fmaf(v.w, w, acc.w);
    }

    acc.x = fmaxf(acc.x, 0.f); acc.y = fmaxf(acc.y, 0.f);
    acc.z = fmaxf(acc.z, 0.f); acc.w = fmaxf(acc.w, 0.f);
    if (MODE == 1) {
        float4 r = ((const float4*)res)[(size_t)warp * 32 + lane];
        acc.x += r.x; acc.y += r.y; acc.z += r.z; acc.w += r.w;
    }
    if (outF)
        ((float4*)outF)[(size_t)warp * 32 + lane] = acc;

    __nv_bfloat16 h0, h1, h2, h3, l0, l1, l2, l3;
    split2(acc.x, h0, l0); split2(acc.y, h1, l1);
    split2(acc.z, h2, l2); split2(acc.w, h3, l3);
    uint2 uh, ul;
    uh.x = pack_bf(h0, h1); uh.y = pack_bf(h2, h3);
    ul.x = pack_bf(l0, l1); ul.y = pack_bf(l2, l3);
    *(uint2*)&outH[(size_t)warp * 128 + lane * 4] = uh;
    *(uint2*)&outL[(size_t)warp * 128 + lane * 4] = ul;
}

// ---------------------------------------------------------------------------
// Final aggregation (F=40) fused with log_softmax; writes d_out directly.
// ---------------------------------------------------------------------------
__global__ void agg40_lsm_kernel(const float* __restrict__ h,
                                 const int* __restrict__ rowptr,
                                 const int2* __restrict__ esw,
                                 float* __restrict__ out, int n) {
    int warp = (blockIdx.x * blockDim.x + threadIdx.x) >> 5;
    int lane = threadIdx.x & 31;
    if (warp >= n) return;
    int beg = rowptr[warp];
    int end = rowptr[warp + 1];

    float a0 = 0.f, a1 = 0.f;
    for (int j = beg; j < end; ++j) {
        int2 sw = __ldg(&esw[j]);
        float w = __int_as_float(sw.y);
        const float* hp = h + (size_t)sw.x * F_OUT;
        a0 = fmaf(__ldg(&hp[lane]), w, a0);
        if (lane < 8) a1 = fmaf(__ldg(&hp[32 + lane]), w, a1);
    }

    float m = a0;
    if (lane < 8) m = fmaxf(m, a1);
#pragma unroll
    for (int o = 16; o > 0; o >>= 1)
        m = fmaxf(m, __shfl_xor_sync(0xffffffffu, m, o));

    float s = expf(a0 - m) + ((lane < 8) ? expf(a1 - m) : 0.f);
#pragma unroll
    for (int o = 16; o > 0; o >>= 1)
        s += __shfl_xor_sync(0xffffffffu, s, o);
    float lse = logf(s);

    out[(size_t)warp * F_OUT + lane] = a0 - m - lse;
    if (lane < 8)
        out[(size_t)warp * F_OUT + 32 + lane] = a1 - m - lse;
}

// ---------------------------------------------------------------------------
// Launch
// ---------------------------------------------------------------------------
extern "C" void kernel_launch(void* const* d_in, const int* in_sizes, int n_in,
                              void* d_out, int out_size) {
    const float* x   = (const float*)d_in[0];
    const int*   src = (const int*)  d_in[1];
    const int*   tgt = (const int*)  d_in[2];
    const float* ew  = (const float*)d_in[3];
    const float* W0  = (const float*)d_in[4];
    const float* b0  = (const float*)d_in[5];
    const float* W1  = (const float*)d_in[6];
    const float* b1  = (const float*)d_in[7];
    const float* W2  = (const float*)d_in[8];
    const float* b2  = (const float*)d_in[9];
    const float* W3  = (const float*)d_in[10];
    const float* b3  = (const float*)d_in[11];
    float* out = (float*)d_out;

    float *h, *x0;
    __nv_bfloat16 *xh, *xl, *p0h, *p0l, *p1h, *p1l;
    __nv_bfloat16 *w0h, *w0l, *w1h, *w1l, *w2h, *w2l, *w3h, *w3l;
    int *deg, *rowptr, *cursor;
    int2* esw;
    cudaGetSymbolAddress((void**)&h,   g_h);
    cudaGetSymbolAddress((void**)&x0,  g_x0);
    cudaGetSymbolAddress((void**)&xh,  g_xh);
    cudaGetSymbolAddress((void**)&xl,  g_xl);
    cudaGetSymbolAddress((void**)&p0h, g_p0h);
    cudaGetSymbolAddress((void**)&p0l, g_p0l);
    cudaGetSymbolAddress((void**)&p1h, g_p1h);
    cudaGetSymbolAddress((void**)&p1l, g_p1l);
    cudaGetSymbolAddress((void**)&w0h, g_w0h);
    cudaGetSymbolAddress((void**)&w0l, g_w0l);
    cudaGetSymbolAddress((void**)&w1h, g_w1h);
    cudaGetSymbolAddress((void**)&w1l, g_w1l);
    cudaGetSymbolAddress((void**)&w2h, g_w2h);
    cudaGetSymbolAddress((void**)&w2l, g_w2l);
    cudaGetSymbolAddress((void**)&w3h, g_w3h);
    cudaGetSymbolAddress((void**)&w3l, g_w3l);
    cudaGetSymbolAddress((void**)&deg,    g_deg);
    cudaGetSymbolAddress((void**)&rowptr, g_rowptr);
    cudaGetSymbolAddress((void**)&cursor, g_cursor);
    cudaGetSymbolAddress((void**)&esw,    g_esw);

    const int M = NNODES;
    const int E = NEDGES;
    const int NTILES = (M + 127) / 128;

    // Dynamic smem: 2 stages × (Ah+Al+Wh+Wl) tiles.
    const int SMEM_128 = 2 * (2 * 128 * 40 + 2 * 128 * 40) * 2;   // 81920
    const int SMEM_64  = 2 * (2 * 128 * 40 + 2 *  64 * 40) * 2;   // 61440
    cudaFuncSetAttribute(gemm_mma_kernel<F_IN,  F_HID, 128>,
                         cudaFuncAttributeMaxDynamicSharedMemorySize, SMEM_128);
    cudaFuncSetAttribute(gemm_mma_kernel<F_HID, F_HID, 128>,
                         cudaFuncAttributeMaxDynamicSharedMemorySize, SMEM_128);
    cudaFuncSetAttribute(gemm_mma_kernel<F_HID, F_OUT, 64>,
                         cudaFuncAttributeMaxDynamicSharedMemorySize, SMEM_64);

    // Persistent grids at full residency (148 SMs; 2 blocks/SM @80KB, 3 @60KB).
    const int G128 = 296;
    const int G64  = 444;

    const int agg_blocks = (M + 7) / 8;

    // Order chosen so the ncu capture slot (previously fill_kernel, 4th launch)
    // lands on the layer-0 GEMM.
    // 0: convert_x  1: convert_w_all  2: zero  3: GEMM0  4: hist ...
    {
        int n4 = M * F_IN / 4;
        convert_x_kernel<<<(n4 + 255) / 256, 256>>>(x, xh, xl, n4);
        int tot = 128 * 256 + 128 * 128 + 128 * 128 + 64 * 128;
        convert_w_all_kernel<<<(tot + 255) / 256, 256>>>(W0, w0h, w0l, W1, w1h, w1l,
                                                         W2, w2h, w2l, W3, w3h, w3l);
    }
    zero_int_kernel<<<(M + 255) / 256, 256>>>(deg, M);

    // ---- layer 0 GEMM (profiling slot) ----
    gemm_mma_kernel<F_IN, F_HID, 128><<<G128, 256, SMEM_128>>>(xh, xl, w0h, w0l, b0, h, M, NTILES);

    // ---- CSR build (independent of GEMM0) ----
    hist_kernel<<<(E + 255) / 256, 256>>>(tgt, deg, E);
    scan_kernel<<<1, 1024>>>(deg, rowptr, cursor, M);
    fill_kernel<<<(E + 255) / 256, 256>>>(src, tgt, ew, cursor, esw, E);

    // ---- layer 0 agg ----
    agg128_kernel<0><<<agg_blocks, 256>>>(h, rowptr, esw, nullptr, x0, p0h, p0l, M);

    // ---- layer 1 ----
    gemm_mma_kernel<F_HID, F_HID, 128><<<G128, 256, SMEM_128>>>(p0h, p0l, w1h, w1l, b1, h, M, NTILES);
    agg128_kernel<0><<<agg_blocks, 256>>>(h, rowptr, esw, nullptr, nullptr, p1h, p1l, M);

    // ---- layer 2 ----
    gemm_mma_kernel<F_HID, F_HID, 128><<<G128, 256, SMEM_128>>>(p1h, p1l, w2h, w2l, b2, h, M, NTILES);
    agg128_kernel<1><<<agg_blocks, 256>>>(h, rowptr, esw, x0, nullptr, p0h, p0l, M);

    // ---- layer 3 ----
    gemm_mma_kernel<F_HID, F_OUT, 64><<<G64, 256, SMEM_64>>>(p0h, p0l, w3h, w3l, b3, h, M, NTILES);
    agg40_lsm_kernel<<<agg_blocks, 256>>>(h, rowptr, esw, out, M);
}

// round 13
// speedup vs baseline: 1.5000x; 1.1119x over previous
#include <cuda_runtime.h>
#include <cuda_bf16.h>
#include <cuda_fp16.h>
#include <math.h>
#include <stdint.h>

// Problem constants (fixed by the reference setup).
#define NNODES 100000
#define NEDGES 1600000
#define F_IN   256
#define F_HID  128
#define F_OUT  40

// ---------------------------------------------------------------------------
// Scratch (device globals; no cudaMalloc allowed)
// ---------------------------------------------------------------------------
__device__ float         g_h  [NNODES * F_HID];     // fp32 GEMM out (layer 3, 40-wide)
__device__ __half        g_hh [NNODES * F_HID];     // fp16 GEMM out (layers 0-2)
__device__ float         g_x0 [NNODES * F_HID];     // residual fp32
__device__ __nv_bfloat16 g_xh [NNODES * F_IN];
__device__ __nv_bfloat16 g_xl [NNODES * F_IN];
__device__ __nv_bfloat16 g_p0h[NNODES * F_HID];
__device__ __nv_bfloat16 g_p0l[NNODES * F_HID];
__device__ __nv_bfloat16 g_p1h[NNODES * F_HID];
__device__ __nv_bfloat16 g_p1l[NNODES * F_HID];
__device__ __nv_bfloat16 g_w0h[128 * 256], g_w0l[128 * 256];
__device__ __nv_bfloat16 g_w1h[128 * 128], g_w1l[128 * 128];
__device__ __nv_bfloat16 g_w2h[128 * 128], g_w2l[128 * 128];
__device__ __nv_bfloat16 g_w3h[ 64 * 128], g_w3l[ 64 * 128];
__device__ int  g_deg   [NNODES];
__device__ int  g_rowptr[NNODES + 1];
__device__ int  g_cursor[NNODES];
__device__ int2 g_esw   [NEDGES];

// ---------------------------------------------------------------------------
// Helpers
// ---------------------------------------------------------------------------
__device__ __forceinline__ void split2(float v, __nv_bfloat16& h, __nv_bfloat16& l) {
    h = __float2bfloat16(v);
    l = __float2bfloat16(v - __bfloat162float(h));
}

__device__ __forceinline__ uint32_t pack_bf(__nv_bfloat16 a, __nv_bfloat16 b) {
    return ((uint32_t)__bfloat16_as_ushort(b) << 16) | (uint32_t)__bfloat16_as_ushort(a);
}

__device__ __forceinline__ void ldsm4(uint32_t* d, const void* p) {
    uint32_t a = (uint32_t)__cvta_generic_to_shared(p);
    asm volatile("ldmatrix.sync.aligned.m8n8.x4.shared.b16 {%0,%1,%2,%3}, [%4];\n"
                 : "=r"(d[0]), "=r"(d[1]), "=r"(d[2]), "=r"(d[3]) : "r"(a));
}

__device__ __forceinline__ void mma_bf16(float* c, const uint32_t* a, const uint32_t* b) {
    asm volatile(
        "mma.sync.aligned.m16n8k16.row.col.f32.bf16.bf16.f32 "
        "{%0,%1,%2,%3}, {%4,%5,%6,%7}, {%8,%9}, {%0,%1,%2,%3};\n"
        : "+f"(c[0]), "+f"(c[1]), "+f"(c[2]), "+f"(c[3])
        : "r"(a[0]), "r"(a[1]), "r"(a[2]), "r"(a[3]), "r"(b[0]), "r"(b[1]));
}

__device__ __forceinline__ void cpa16(void* dst_smem, const void* src, int src_bytes) {
    uint32_t d = (uint32_t)__cvta_generic_to_shared(dst_smem);
    asm volatile("cp.async.cg.shared.global [%0], [%1], 16, %2;\n"
                 :: "r"(d), "l"(src), "r"(src_bytes));
}
__device__ __forceinline__ void cpa_commit() {
    asm volatile("cp.async.commit_group;\n");
}
template<int N>
__device__ __forceinline__ void cpa_wait() {
    asm volatile("cp.async.wait_group %0;\n" :: "n"(N));
}

// ---------------------------------------------------------------------------
// CSR build
// ---------------------------------------------------------------------------
__global__ void zero_int_kernel(int* p, int n) {
    int i = blockIdx.x * blockDim.x + threadIdx.x;
    if (i < n) p[i] = 0;
}

__global__ void hist_kernel(const int* __restrict__ tgt, int* __restrict__ deg, int e) {
    int i = blockIdx.x * blockDim.x + threadIdx.x;
    if (i < e) atomicAdd(&deg[tgt[i]], 1);
}

__global__ void scan_kernel(const int* __restrict__ deg, int* __restrict__ rowptr,
                            int* __restrict__ cursor, int n) {
    __shared__ int sums[1024];
    int t = threadIdx.x;
    const int CH = (n + 1023) >> 10;
    int beg = t * CH;
    int endi = beg + CH; if (endi > n) endi = n;
    int s = 0;
    for (int i = beg; i < endi; ++i) s += deg[i];
    sums[t] = s;
    __syncthreads();
    for (int off = 1; off < 1024; off <<= 1) {
        int v = (t >= off) ? sums[t - off] : 0;
        __syncthreads();
        sums[t] += v;
        __syncthreads();
    }
    int run = (t == 0) ? 0 : sums[t - 1];
    for (int i = beg; i < endi; ++i) {
        rowptr[i] = run;
        cursor[i] = run;
        run += deg[i];
    }
    if (t == 0) rowptr[n] = sums[1023];
}

__global__ void fill_kernel(const int* __restrict__ src, const int* __restrict__ tgt,
                            const float* __restrict__ ew, int* __restrict__ cursor,
                            int2* __restrict__ esw, int e) {
    int i = blockIdx.x * blockDim.x + threadIdx.x;
    if (i < e) {
        int p = atomicAdd(&cursor[tgt[i]], 1);
        esw[p] = make_int2(src[i], __float_as_int(ew[i]));
    }
}

// ---------------------------------------------------------------------------
// Conversion kernels
// ---------------------------------------------------------------------------
__global__ void convert_x_kernel(const float* __restrict__ in,
                                 __nv_bfloat16* __restrict__ hi,
                                 __nv_bfloat16* __restrict__ lo, int n4) {
    int i = blockIdx.x * blockDim.x + threadIdx.x;
    if (i >= n4) return;
    float4 v = ((const float4*)in)[i];
    __nv_bfloat16 h0, h1, h2, h3, l0, l1, l2, l3;
    split2(v.x, h0, l0); split2(v.y, h1, l1);
    split2(v.z, h2, l2); split2(v.w, h3, l3);
    uint2 uh, ul;
    uh.x = pack_bf(h0, h1); uh.y = pack_bf(h2, h3);
    ul.x = pack_bf(l0, l1); ul.y = pack_bf(l2, l3);
    *(uint2*)&hi[(size_t)i * 4] = uh;
    *(uint2*)&lo[(size_t)i * 4] = ul;
}

// All four weights in one launch: transpose + split + pad.
__global__ void convert_w_all_kernel(const float* __restrict__ W0, __nv_bfloat16* oh0, __nv_bfloat16* ol0,
                                     const float* __restrict__ W1, __nv_bfloat16* oh1, __nv_bfloat16* ol1,
                                     const float* __restrict__ W2, __nv_bfloat16* oh2, __nv_bfloat16* ol2,
                                     const float* __restrict__ W3, __nv_bfloat16* oh3, __nv_bfloat16* ol3) {
    const int S0 = 128 * 256, S1 = 128 * 128, S2 = 128 * 128, S3 = 64 * 128;
    int idx = blockIdx.x * blockDim.x + threadIdx.x;
    const float* W; __nv_bfloat16 *oh, *ol; int K, N;
    if (idx < S0)                { W = W0; oh = oh0; ol = ol0; K = 256; N = 128; }
    else if ((idx -= S0) < S1)   { W = W1; oh = oh1; ol = ol1; K = 128; N = 128; }
    else if ((idx -= S1) < S2)   { W = W2; oh = oh2; ol = ol2; K = 128; N = 128; }
    else if ((idx -= S2) < S3)   { W = W3; oh = oh3; ol = ol3; K = 128; N = 40;  }
    else return;
    int n = idx / K, k = idx % K;
    float v = (n < N) ? W[(size_t)k * N + n] : 0.0f;
    __nv_bfloat16 h, l;
    split2(v, h, l);
    oh[idx] = h; ol[idx] = l;
}

// ---------------------------------------------------------------------------
// Persistent tensor-core GEMM (cp.async 2-stage, cross-tile prefetch).
// C = A @ W + bias via 3-term bf16 split. HALF_OUT selects fp16 vs fp32 C.
// ---------------------------------------------------------------------------
template<int K, int NOUT, int BN, int HALF_OUT>
__global__ void __launch_bounds__(256)
gemm_mma_kernel(const __nv_bfloat16* __restrict__ Ah,
                const __nv_bfloat16* __restrict__ Al,
                const __nv_bfloat16* __restrict__ Wh,
                const __nv_bfloat16* __restrict__ Wl,
                const float* __restrict__ bias,
                void* __restrict__ Cv, int M, int ntiles) {
    constexpr int BM  = 128, BK = 32;
    constexpr int BKP = BK + 8;
    constexpr int WARPS_N = BN / 32;
    constexpr int WARPS_M = 8 / WARPS_N;
    constexpr int MT = (BM / WARPS_M) / 16;
    constexpr int NT = 4;
    constexpr int TA = BM * BKP;
    constexpr int TW = BN * BKP;
    constexpr int STAGE = 2 * TA + 2 * TW;
    constexpr int NKI = K / BK;
    static_assert((NKI & 1) == 0, "NKI must be even for cross-tile parity");

    extern __shared__ __align__(16) __nv_bfloat16 sm[];

    const int tid  = threadIdx.x;
    const int wid  = tid >> 5;
    const int lane = tid & 31;
    const int wm   = (wid / WARPS_N) * (MT * 16);
    const int wn   = (wid % WARPS_N) * 32;

    auto load_stage = [&](int s, int row0, int kk) {
        __nv_bfloat16* bAh = sm + s * STAGE;
        __nv_bfloat16* bAl = bAh + TA;
        __nv_bfloat16* bWh = bAl + TA;
        __nv_bfloat16* bWl = bWh + TW;
#pragma unroll
        for (int t = tid; t < BM * 4; t += 256) {
            int r = t >> 2, c = (t & 3) * 8;
            int grow = row0 + r;
            size_t ridx = (grow < M) ? (size_t)grow : 0;
            int nb = (grow < M) ? 16 : 0;
            cpa16(&bAh[r * BKP + c], &Ah[ridx * K + kk + c], nb);
            cpa16(&bAl[r * BKP + c], &Al[ridx * K + kk + c], nb);
        }
#pragma unroll
        for (int t = tid; t < BN * 4; t += 256) {
            int r = t >> 2, c = (t & 3) * 8;
            cpa16(&bWh[r * BKP + c], &Wh[(size_t)r * K + kk + c], 16);
            cpa16(&bWl[r * BKP + c], &Wl[(size_t)r * K + kk + c], 16);
        }
    };

    int tile = blockIdx.x;
    if (tile >= ntiles) return;
    int row0 = tile * BM;

    load_stage(0, row0, 0);
    cpa_commit();

    const int rbase = lane >> 2;
    const int cbase = (lane & 3) * 2;

    while (true) {
        int next_tile = tile + gridDim.x;
        int next_row0 = next_tile * BM;

        float acc[MT][NT][4];
#pragma unroll
        for (int i = 0; i < MT; ++i)
#pragma unroll
            for (int j = 0; j < NT; ++j)
#pragma unroll
                for (int q = 0; q < 4; ++q) acc[i][j][q] = 0.0f;

        for (int it = 0; it < NKI; ++it) {
            if (it + 1 < NKI)
                load_stage((it + 1) & 1, row0, (it + 1) * BK);
            else if (next_tile < ntiles)
                load_stage(0, next_row0, 0);
            cpa_commit();
            cpa_wait<1>();
            __syncthreads();

            const __nv_bfloat16* bAh = sm + (it & 1) * STAGE;
            const __nv_bfloat16* bAl = bAh + TA;
            const __nv_bfloat16* bWh = bAl + TA;
            const __nv_bfloat16* bWl = bWh + TW;

#pragma unroll
            for (int ks = 0; ks < BK; ks += 16) {
                uint32_t ah[MT][4], al[MT][4];
#pragma unroll
                for (int mt = 0; mt < MT; ++mt) {
                    int r = wm + mt * 16 + (lane & 15);
                    int c = ks + ((lane >> 4) << 3);
                    ldsm4(ah[mt], &bAh[r * BKP + c]);
                    ldsm4(al[mt], &bAl[r * BKP + c]);
                }
                uint32_t bh[NT][2], bl[NT][2];
#pragma unroll
                for (int np = 0; np < NT / 2; ++np) {
                    int n = wn + np * 16 + (lane & 7) + ((lane >> 4) << 3);
                    int c = ks + (((lane >> 3) & 1) << 3);
                    uint32_t t4[4];
                    ldsm4(t4, &bWh[n * BKP + c]);
                    bh[2 * np][0] = t4[0]; bh[2 * np][1] = t4[1];
                    bh[2 * np + 1][0] = t4[2]; bh[2 * np + 1][1] = t4[3];
                    ldsm4(t4, &bWl[n * BKP + c]);
                    bl[2 * np][0] = t4[0]; bl[2 * np][1] = t4[1];
                    bl[2 * np + 1][0] = t4[2]; bl[2 * np + 1][1] = t4[3];
                }
#pragma unroll
                for (int mt = 0; mt < MT; ++mt)
#pragma unroll
                    for (int nt = 0; nt < NT; ++nt) {
                        mma_bf16(acc[mt][nt], ah[mt], bh[nt]);
                        mma_bf16(acc[mt][nt], ah[mt], bl[nt]);
                        mma_bf16(acc[mt][nt], al[mt], bh[nt]);
                    }
            }
            __syncthreads();
        }

        // epilogue (overlaps the in-flight next-tile loads)
#pragma unroll
        for (int mt = 0; mt < MT; ++mt)
#pragma unroll
            for (int nt = 0; nt < NT; ++nt) {
                int col = wn + nt * 8 + cbase;
                if (col >= NOUT) continue;
                float bx = bias[col], by = bias[col + 1];
#pragma unroll
                for (int h = 0; h < 2; ++h) {
                    int row = row0 + wm + mt * 16 + rbase + h * 8;
                    if (row < M) {
                        float cx = acc[mt][nt][h * 2 + 0] + bx;
                        float cy = acc[mt][nt][h * 2 + 1] + by;
                        if (HALF_OUT) {
                            __half2 v = __floats2half2_rn(cx, cy);
                            *(__half2*)&((__half*)Cv)[(size_t)row * NOUT + col] = v;
                        } else {
                            float2 v = make_float2(cx, cy);
                            *(float2*)&((float*)Cv)[(size_t)row * NOUT + col] = v;
                        }
                    }
                }
            }

        if (next_tile >= ntiles) break;
        tile = next_tile;
        row0 = next_row0;
    }
}

// ---------------------------------------------------------------------------
// Aggregation (gather-CSR) over fp16 messages, F=128, warp per node.
// Each lane handles 4 features (8 bytes/row). fp32 accumulate.
// MODE 0: relu(sum);  MODE 1: relu(sum) + res
// ---------------------------------------------------------------------------
template<int MODE>
__global__ void agg128_kernel(const __half* __restrict__ h,
                              const int* __restrict__ rowptr,
                              const int2* __restrict__ esw,
                              const float* __restrict__ res,
                              float* __restrict__ outF,
                              __nv_bfloat16* __restrict__ outH,
                              __nv_bfloat16* __restrict__ outL, int n) {
    int warp = (blockIdx.x * blockDim.x + threadIdx.x) >> 5;
    int lane = threadIdx.x & 31;
    if (warp >= n) return;
    int beg = rowptr[warp];
    int end = rowptr[warp + 1];

    const uint2* h2 = (const uint2*)h;      // 4 halves per uint2; row = 32 uint2
    float4 acc = make_float4(0.f, 0.f, 0.f, 0.f);

    auto accum = [&](uint2 u, float w) {
        float2 f0 = __half22float2(*(__half2*)&u.x);
        float2 f1 = __half22float2(*(__half2*)&u.y);
        acc.x = fmaf(f0.x, w, acc.x); acc.y = fmaf(f0.y, w, acc.y);
        acc.z = fmaf(f1.x, w, acc.z); acc.w = fmaf(f1.y, w, acc.w);
    };

    int j = beg;
    for (; j + 3 < end; j += 4) {
        int2 sw0 = __ldg(&esw[j]);
        int2 sw1 = __ldg(&esw[j + 1]);
        int2 sw2 = __ldg(&esw[j + 2]);
        int2 sw3 = __ldg(&esw[j + 3]);
        uint2 v0 = __ldg(&h2[(size_t)sw0.x * 32 + lane]);
        uint2 v1 = __ldg(&h2[(size_t)sw1.x * 32 + lane]);
        uint2 v2 = __ldg(&h2[(size_t)sw2.x * 32 + lane]);
        uint2 v3 = __ldg(&h2[(size_t)sw3.x * 32 + lane]);
        accum(v0, __int_as_float(sw0.y));
        accum(v1, __int_as_float(sw1.y));
        accum(v2, __int_as_float(sw2.y));
        accum(v3, __int_as_float(sw3.y));
    }
    for (; j < end; ++j) {
        int2 sw = __ldg(&esw[j]);
        uint2 v = __ldg(&h2[(size_t)sw.x * 32 + lane]);
        accum(v, __int_as_float(sw.y));
    }

    acc.x = fmaxf(acc.x, 0.f); acc.y = fmaxf(acc.y, 0.f);
    acc.z = fmaxf(acc.z, 0.f); acc.w = fmaxf(acc.w, 0.f);
    if (MODE == 1) {
        float4 r = ((const float4*)res)[(size_t)warp * 32 + lane];
        acc.x += r.x; acc.y += r.y; acc.z += r.z; acc.w += r.w;
    }
    if (outF)
        ((float4*)outF)[(size_t)warp * 32 + lane] = acc;

    __nv_bfloat16 h0, h1, hh2, h3, l0, l1, l2, l3;
    split2(acc.x, h0, l0); split2(acc.y, h1, l1);
    split2(acc.z, hh2, l2); split2(acc.w, h3, l3);
    uint2 uh, ul;
    uh.x = pack_bf(h0, h1); uh.y = pack_bf(hh2, h3);
    ul.x = pack_bf(l0, l1); ul.y = pack_bf(l2, l3);
    *(uint2*)&outH[(size_t)warp * 128 + lane * 4] = uh;
    *(uint2*)&outL[(size_t)warp * 128 + lane * 4] = ul;
}

// ---------------------------------------------------------------------------
// Final aggregation (F=40, fp32) fused with log_softmax; writes d_out.
// ---------------------------------------------------------------------------
__global__ void agg40_lsm_kernel(const float* __restrict__ h,
                                 const int* __restrict__ rowptr,
                                 const int2* __restrict__ esw,
                                 float* __restrict__ out, int n) {
    int warp = (blockIdx.x * blockDim.x + threadIdx.x) >> 5;
    int lane = threadIdx.x & 31;
    if (warp >= n) return;
    int beg = rowptr[warp];
    int end = rowptr[warp + 1];

    float a0 = 0.f, a1 = 0.f;
    for (int j = beg; j < end; ++j) {
        int2 sw = __ldg(&esw[j]);
        float w = __int_as_float(sw.y);
        const float* hp = h + (size_t)sw.x * F_OUT;
        a0 = fmaf(__ldg(&hp[lane]), w, a0);
        if (lane < 8) a1 = fmaf(__ldg(&hp[32 + lane]), w, a1);
    }

    float m = a0;
    if (lane < 8) m = fmaxf(m, a1);
#pragma unroll
    for (int o = 16; o > 0; o >>= 1)
        m = fmaxf(m, __shfl_xor_sync(0xffffffffu, m, o));

    float s = expf(a0 - m) + ((lane < 8) ? expf(a1 - m) : 0.f);
#pragma unroll
    for (int o = 16; o > 0; o >>= 1)
        s += __shfl_xor_sync(0xffffffffu, s, o);
    float lse = logf(s);

    out[(size_t)warp * F_OUT + lane] = a0 - m - lse;
    if (lane < 8)
        out[(size_t)warp * F_OUT + 32 + lane] = a1 - m - lse;
}

// ---------------------------------------------------------------------------
// Launch
// ---------------------------------------------------------------------------
extern "C" void kernel_launch(void* const* d_in, const int* in_sizes, int n_in,
                              void* d_out, int out_size) {
    const float* x   = (const float*)d_in[0];
    const int*   src = (const int*)  d_in[1];
    const int*   tgt = (const int*)  d_in[2];
    const float* ew  = (const float*)d_in[3];
    const float* W0  = (const float*)d_in[4];
    const float* b0  = (const float*)d_in[5];
    const float* W1  = (const float*)d_in[6];
    const float* b1  = (const float*)d_in[7];
    const float* W2  = (const float*)d_in[8];
    const float* b2  = (const float*)d_in[9];
    const float* W3  = (const float*)d_in[10];
    const float* b3  = (const float*)d_in[11];
    float* out = (float*)d_out;

    float *h, *x0;
    __half* hh;
    __nv_bfloat16 *xh, *xl, *p0h, *p0l, *p1h, *p1l;
    __nv_bfloat16 *w0h, *w0l, *w1h, *w1l, *w2h, *w2l, *w3h, *w3l;
    int *deg, *rowptr, *cursor;
    int2* esw;
    cudaGetSymbolAddress((void**)&h,   g_h);
    cudaGetSymbolAddress((void**)&hh,  g_hh);
    cudaGetSymbolAddress((void**)&x0,  g_x0);
    cudaGetSymbolAddress((void**)&xh,  g_xh);
    cudaGetSymbolAddress((void**)&xl,  g_xl);
    cudaGetSymbolAddress((void**)&p0h, g_p0h);
    cudaGetSymbolAddress((void**)&p0l, g_p0l);
    cudaGetSymbolAddress((void**)&p1h, g_p1h);
    cudaGetSymbolAddress((void**)&p1l, g_p1l);
    cudaGetSymbolAddress((void**)&w0h, g_w0h);
    cudaGetSymbolAddress((void**)&w0l, g_w0l);
    cudaGetSymbolAddress((void**)&w1h, g_w1h);
    cudaGetSymbolAddress((void**)&w1l, g_w1l);
    cudaGetSymbolAddress((void**)&w2h, g_w2h);
    cudaGetSymbolAddress((void**)&w2l, g_w2l);
    cudaGetSymbolAddress((void**)&w3h, g_w3h);
    cudaGetSymbolAddress((void**)&w3l, g_w3l);
    cudaGetSymbolAddress((void**)&deg,    g_deg);
    cudaGetSymbolAddress((void**)&rowptr, g_rowptr);
    cudaGetSymbolAddress((void**)&cursor, g_cursor);
    cudaGetSymbolAddress((void**)&esw,    g_esw);

    const int M = NNODES;
    const int E = NEDGES;
    const int NTILES = (M + 127) / 128;

    const int SMEM_128 = 2 * (2 * 128 * 40 + 2 * 128 * 40) * 2;   // 81920
    const int SMEM_64  = 2 * (2 * 128 * 40 + 2 *  64 * 40) * 2;   // 61440
    cudaFuncSetAttribute(gemm_mma_kernel<F_IN,  F_HID, 128, 1>,
                         cudaFuncAttributeMaxDynamicSharedMemorySize, SMEM_128);
    cudaFuncSetAttribute(gemm_mma_kernel<F_HID, F_HID, 128, 1>,
                         cudaFuncAttributeMaxDynamicSharedMemorySize, SMEM_128);
    cudaFuncSetAttribute(gemm_mma_kernel<F_HID, F_OUT, 64, 0>,
                         cudaFuncAttributeMaxDynamicSharedMemorySize, SMEM_64);

    const int G128 = 296;
    const int G64  = 444;
    const int agg_blocks = (M + 7) / 8;

    // 0: convert_x  1: convert_w_all  2: zero  3: GEMM0 (ncu slot)  4: hist ...
    {
        int n4 = M * F_IN / 4;
        convert_x_kernel<<<(n4 + 255) / 256, 256>>>(x, xh, xl, n4);
        int tot = 128 * 256 + 128 * 128 + 128 * 128 + 64 * 128;
        convert_w_all_kernel<<<(tot + 255) / 256, 256>>>(W0, w0h, w0l, W1, w1h, w1l,
                                                         W2, w2h, w2l, W3, w3h, w3l);
    }
    zero_int_kernel<<<(M + 255) / 256, 256>>>(deg, M);

    // ---- layer 0 GEMM (fp16 out) ----
    gemm_mma_kernel<F_IN, F_HID, 128, 1><<<G128, 256, SMEM_128>>>(xh, xl, w0h, w0l, b0, hh, M, NTILES);

    // ---- CSR build ----
    hist_kernel<<<(E + 255) / 256, 256>>>(tgt, deg, E);
    scan_kernel<<<1, 1024>>>(deg, rowptr, cursor, M);
    fill_kernel<<<(E + 255) / 256, 256>>>(src, tgt, ew, cursor, esw, E);

    // ---- layer 0 agg ----
    agg128_kernel<0><<<agg_blocks, 256>>>(hh, rowptr, esw, nullptr, x0, p0h, p0l, M);

    // ---- layer 1 ----
    gemm_mma_kernel<F_HID, F_HID, 128, 1><<<G128, 256, SMEM_128>>>(p0h, p0l, w1h, w1l, b1, hh, M, NTILES);
    agg128_kernel<0><<<agg_blocks, 256>>>(hh, rowptr, esw, nullptr, nullptr, p1h, p1l, M);

    // ---- layer 2 ----
    gemm_mma_kernel<F_HID, F_HID, 128, 1><<<G128, 256, SMEM_128>>>(p1h, p1l, w2h, w2l, b2, hh, M, NTILES);
    agg128_kernel<1><<<agg_blocks, 256>>>(hh, rowptr, esw, x0, nullptr, p0h, p0l, M);

    // ---- layer 3 (fp32 logits path) ----
    gemm_mma_kernel<F_HID, F_OUT, 64, 0><<<G64, 256, SMEM_64>>>(p0h, p0l, w3h, w3l, b3, h, M, NTILES);
    agg40_lsm_kernel<<<agg_blocks, 256>>>(h, rowptr, esw, out, M);
}

// round 14
// speedup vs baseline: 1.6762x; 1.1175x over previous
#include <cuda_runtime.h>
#include <cuda_bf16.h>
#include <cuda_fp16.h>
#include <math.h>
#include <stdint.h>

// Problem constants (fixed by the reference setup).
#define NNODES 100000
#define NEDGES 1600000
#define F_IN   256
#define F_HID  128
#define F_OUT  40

// ---------------------------------------------------------------------------
// Scratch (device globals; no cudaMalloc allowed)
// ---------------------------------------------------------------------------
__device__ float  g_h   [NNODES * F_OUT];      // fp32 GEMM out (layer 3)
__device__ __half g_hh  [NNODES * F_HID];      // fp16 GEMM out (layers 0-2)
__device__ __half g_act0[NNODES * F_HID];      // x0 (GEMM1 input + residual)
__device__ __half g_act1[NNODES * F_HID];      // x1
__device__ __half g_act2[NNODES * F_HID];      // x2
__device__ __half g_xf  [NNODES * F_IN];       // input x in fp16
// Transposed, padded, fp16-split weights: Wt[n][k]
__device__ __half g_w0h[128 * 256], g_w0l[128 * 256];
__device__ __half g_w1h[128 * 128], g_w1l[128 * 128];
__device__ __half g_w2h[128 * 128], g_w2l[128 * 128];
__device__ __half g_w3h[ 64 * 128], g_w3l[ 64 * 128];
// CSR
__device__ int  g_deg   [NNODES];
__device__ int  g_rowptr[NNODES + 1];
__device__ int  g_cursor[NNODES];
__device__ int2 g_esw   [NEDGES];

// ---------------------------------------------------------------------------
// Helpers
// ---------------------------------------------------------------------------
__device__ __forceinline__ void ldsm4(uint32_t* d, const void* p) {
    uint32_t a = (uint32_t)__cvta_generic_to_shared(p);
    asm volatile("ldmatrix.sync.aligned.m8n8.x4.shared.b16 {%0,%1,%2,%3}, [%4];\n"
                 : "=r"(d[0]), "=r"(d[1]), "=r"(d[2]), "=r"(d[3]) : "r"(a));
}

__device__ __forceinline__ void mma_f16(float* c, const uint32_t* a, const uint32_t* b) {
    asm volatile(
        "mma.sync.aligned.m16n8k16.row.col.f32.f16.f16.f32 "
        "{%0,%1,%2,%3}, {%4,%5,%6,%7}, {%8,%9}, {%0,%1,%2,%3};\n"
        : "+f"(c[0]), "+f"(c[1]), "+f"(c[2]), "+f"(c[3])
        : "r"(a[0]), "r"(a[1]), "r"(a[2]), "r"(a[3]), "r"(b[0]), "r"(b[1]));
}

__device__ __forceinline__ void cpa16(void* dst_smem, const void* src, int src_bytes) {
    uint32_t d = (uint32_t)__cvta_generic_to_shared(dst_smem);
    asm volatile("cp.async.cg.shared.global [%0], [%1], 16, %2;\n"
                 :: "r"(d), "l"(src), "r"(src_bytes));
}
__device__ __forceinline__ void cpa_commit() {
    asm volatile("cp.async.commit_group;\n");
}
template<int N>
__device__ __forceinline__ void cpa_wait() {
    asm volatile("cp.async.wait_group %0;\n" :: "n"(N));
}

// ---------------------------------------------------------------------------
// CSR build
// ---------------------------------------------------------------------------
__global__ void zero_int_kernel(int* p, int n) {
    int i = blockIdx.x * blockDim.x + threadIdx.x;
    if (i < n) p[i] = 0;
}

__global__ void hist_kernel(const int* __restrict__ tgt, int* __restrict__ deg, int e) {
    int i = blockIdx.x * blockDim.x + threadIdx.x;
    if (i < e) atomicAdd(&deg[tgt[i]], 1);
}

__global__ void scan_kernel(const int* __restrict__ deg, int* __restrict__ rowptr,
                            int* __restrict__ cursor, int n) {
    __shared__ int sums[1024];
    int t = threadIdx.x;
    const int CH = (n + 1023) >> 10;
    int beg = t * CH;
    int endi = beg + CH; if (endi > n) endi = n;
    int s = 0;
    for (int i = beg; i < endi; ++i) s += deg[i];
    sums[t] = s;
    __syncthreads();
    for (int off = 1; off < 1024; off <<= 1) {
        int v = (t >= off) ? sums[t - off] : 0;
        __syncthreads();
        sums[t] += v;
        __syncthreads();
    }
    int run = (t == 0) ? 0 : sums[t - 1];
    for (int i = beg; i < endi; ++i) {
        rowptr[i] = run;
        cursor[i] = run;
        run += deg[i];
    }
    if (t == 0) rowptr[n] = sums[1023];
}

__global__ void fill_kernel(const int* __restrict__ src, const int* __restrict__ tgt,
                            const float* __restrict__ ew, int* __restrict__ cursor,
                            int2* __restrict__ esw, int e) {
    int i = blockIdx.x * blockDim.x + threadIdx.x;
    if (i < e) {
        int p = atomicAdd(&cursor[tgt[i]], 1);
        esw[p] = make_int2(src[i], __float_as_int(ew[i]));
    }
}

// ---------------------------------------------------------------------------
// Conversion kernels
// ---------------------------------------------------------------------------
__global__ void convert_x_kernel(const float* __restrict__ in,
                                 __half* __restrict__ o, int n4) {
    int i = blockIdx.x * blockDim.x + threadIdx.x;
    if (i >= n4) return;
    float4 v = ((const float4*)in)[i];
    __half2 a = __floats2half2_rn(v.x, v.y);
    __half2 b = __floats2half2_rn(v.z, v.w);
    uint2 u;
    u.x = *(uint32_t*)&a;
    u.y = *(uint32_t*)&b;
    *(uint2*)&o[(size_t)i * 4] = u;
}

// All four weights in one launch: transpose + fp16-split + pad.
__global__ void convert_w_all_kernel(const float* __restrict__ W0, __half* oh0, __half* ol0,
                                     const float* __restrict__ W1, __half* oh1, __half* ol1,
                                     const float* __restrict__ W2, __half* oh2, __half* ol2,
                                     const float* __restrict__ W3, __half* oh3, __half* ol3) {
    const int S0 = 128 * 256, S1 = 128 * 128, S2 = 128 * 128, S3 = 64 * 128;
    int idx = blockIdx.x * blockDim.x + threadIdx.x;
    const float* W; __half *oh, *ol; int K, N;
    if (idx < S0)                { W = W0; oh = oh0; ol = ol0; K = 256; N = 128; }
    else if ((idx -= S0) < S1)   { W = W1; oh = oh1; ol = ol1; K = 128; N = 128; }
    else if ((idx -= S1) < S2)   { W = W2; oh = oh2; ol = ol2; K = 128; N = 128; }
    else if ((idx -= S2) < S3)   { W = W3; oh = oh3; ol = ol3; K = 128; N = 40;  }
    else return;
    int n = idx / K, k = idx % K;
    float v = (n < N) ? W[(size_t)k * N + n] : 0.0f;
    __half h = __float2half(v);
    __half l = __float2half(v - __half2float(h));
    oh[idx] = h; ol[idx] = l;
}

// ---------------------------------------------------------------------------
// Persistent tensor-core GEMM, 3-stage cp.async ring, cross-tile prefetch.
// C = A @ (Wh + Wl) + bias.  A fp16 [M][K]; W fp16-split, transposed [BN][K].
// BM=128, BK=32, 256 threads (8 warps). HALF_OUT selects fp16 vs fp32 C.
// ---------------------------------------------------------------------------
template<int K, int NOUT, int BN, int HALF_OUT>
__global__ void __launch_bounds__(256)
gemm_mma_kernel(const __half* __restrict__ A,
                const __half* __restrict__ Wh,
                const __half* __restrict__ Wl,
                const float* __restrict__ bias,
                void* __restrict__ Cv, int M, int ntiles) {
    constexpr int BM  = 128, BK = 32;
    constexpr int BKP = BK + 8;                // 80B row stride, conflict-free LDSM
    constexpr int WARPS_N = BN / 32;           // 4 or 2
    constexpr int WARPS_M = 8 / WARPS_N;       // 2 or 4
    constexpr int MT = (BM / WARPS_M) / 16;    // 4 or 2
    constexpr int NT = 4;
    constexpr int TA = BM * BKP;
    constexpr int TW = BN * BKP;
    constexpr int STAGE = TA + 2 * TW;         // A, Wh, Wl
    constexpr int NKI = K / BK;

    extern __shared__ __align__(16) __half sm[];

    const int tid  = threadIdx.x;
    const int wid  = tid >> 5;
    const int lane = tid & 31;
    const int wm   = (wid / WARPS_N) * (MT * 16);
    const int wn   = (wid % WARPS_N) * 32;

    auto load_stage = [&](int s, int row0, int kk) {
        __half* bA  = sm + s * STAGE;
        __half* bWh = bA + TA;
        __half* bWl = bWh + TW;
#pragma unroll
        for (int t = tid; t < BM * 4; t += 256) {
            int r = t >> 2, c = (t & 3) * 8;
            int grow = row0 + r;
            size_t ridx = (grow < M) ? (size_t)grow : 0;
            int nb = (grow < M) ? 16 : 0;
            cpa16(&bA[r * BKP + c], &A[ridx * K + kk + c], nb);
        }
#pragma unroll
        for (int t = tid; t < BN * 4; t += 256) {
            int r = t >> 2, c = (t & 3) * 8;
            cpa16(&bWh[r * BKP + c], &Wh[(size_t)r * K + kk + c], 16);
            cpa16(&bWl[r * BKP + c], &Wl[(size_t)r * K + kk + c], 16);
        }
    };

    int ct = blockIdx.x;
    if (ct >= ntiles) return;

    // load cursor
    int lt = ct, lk = 0;
    auto adv = [&]() { if (++lk == NKI) { lk = 0; lt += gridDim.x; } };

    // preload stages 0, 1 (each its own commit group)
    load_stage(0, lt * BM, lk * BK); cpa_commit(); adv();
    if (lt < ntiles) { load_stage(1, lt * BM, lk * BK); adv(); }
    cpa_commit();

    int sbuf = 2, cbuf = 0;
    const int rbase = lane >> 2;
    const int cbase = (lane & 3) * 2;

    for (int ctile = ct; ctile < ntiles; ctile += gridDim.x) {
        float acc[MT][NT][4];
#pragma unroll
        for (int i = 0; i < MT; ++i)
#pragma unroll
            for (int j = 0; j < NT; ++j)
#pragma unroll
                for (int q = 0; q < 4; ++q) acc[i][j][q] = 0.0f;

        for (int ck = 0; ck < NKI; ++ck) {
            if (lt < ntiles) { load_stage(sbuf, lt * BM, lk * BK); adv(); }
            cpa_commit();
            cpa_wait<2>();           // oldest (cbuf's) group complete
            __syncthreads();

            const __half* bA  = sm + cbuf * STAGE;
            const __half* bWh = bA + TA;
            const __half* bWl = bWh + TW;

#pragma unroll
            for (int ks = 0; ks < BK; ks += 16) {
                uint32_t af[MT][4];
#pragma unroll
                for (int mt = 0; mt < MT; ++mt) {
                    int r = wm + mt * 16 + (lane & 15);
                    int c = ks + ((lane >> 4) << 3);
                    ldsm4(af[mt], &bA[r * BKP + c]);
                }
                uint32_t bh[NT][2], bl[NT][2];
#pragma unroll
                for (int np = 0; np < NT / 2; ++np) {
                    int n = wn + np * 16 + (lane & 7) + ((lane >> 4) << 3);
                    int c = ks + (((lane >> 3) & 1) << 3);
                    uint32_t t4[4];
                    ldsm4(t4, &bWh[n * BKP + c]);
                    bh[2 * np][0] = t4[0]; bh[2 * np][1] = t4[1];
                    bh[2 * np + 1][0] = t4[2]; bh[2 * np + 1][1] = t4[3];
                    ldsm4(t4, &bWl[n * BKP + c]);
                    bl[2 * np][0] = t4[0]; bl[2 * np][1] = t4[1];
                    bl[2 * np + 1][0] = t4[2]; bl[2 * np + 1][1] = t4[3];
                }
#pragma unroll
                for (int mt = 0; mt < MT; ++mt)
#pragma unroll
                    for (int nt = 0; nt < NT; ++nt) {
                        mma_f16(acc[mt][nt], af[mt], bh[nt]);
                        mma_f16(acc[mt][nt], af[mt], bl[nt]);
                    }
            }
            __syncthreads();
            sbuf = (sbuf == 2) ? 0 : sbuf + 1;
            cbuf = (cbuf == 2) ? 0 : cbuf + 1;
        }

        // epilogue (registers only; overlaps in-flight next-tile loads)
        int row0 = ctile * BM;
#pragma unroll
        for (int mt = 0; mt < MT; ++mt)
#pragma unroll
            for (int nt = 0; nt < NT; ++nt) {
                int col = wn + nt * 8 + cbase;
                if (col >= NOUT) continue;
                float bx = bias[col], by = bias[col + 1];
#pragma unroll
                for (int h = 0; h < 2; ++h) {
                    int row = row0 + wm + mt * 16 + rbase + h * 8;
                    if (row < M) {
                        float cx = acc[mt][nt][h * 2 + 0] + bx;
                        float cy = acc[mt][nt][h * 2 + 1] + by;
                        if (HALF_OUT) {
                            __half2 v = __floats2half2_rn(cx, cy);
                            *(__half2*)&((__half*)Cv)[(size_t)row * NOUT + col] = v;
                        } else {
                            float2 v = make_float2(cx, cy);
                            *(float2*)&((float*)Cv)[(size_t)row * NOUT + col] = v;
                        }
                    }
                }
            }
    }
}

// ---------------------------------------------------------------------------
// Aggregation (gather-CSR) over fp16 messages, F=128, warp per node.
// fp32 accumulate; writes fp16 activation. MODE 1 adds fp16 residual.
// ---------------------------------------------------------------------------
template<int MODE>
__global__ void agg128_kernel(const __half* __restrict__ h,
                              const int* __restrict__ rowptr,
                              const int2* __restrict__ esw,
                              const __half* __restrict__ res,
                              __half* __restrict__ out, int n) {
    int warp = (blockIdx.x * blockDim.x + threadIdx.x) >> 5;
    int lane = threadIdx.x & 31;
    if (warp >= n) return;
    int beg = rowptr[warp];
    int end = rowptr[warp + 1];

    const uint2* h2 = (const uint2*)h;      // 4 halves per uint2; 32 per row
    float4 acc = make_float4(0.f, 0.f, 0.f, 0.f);

    auto accum = [&](uint2 u, float w) {
        float2 f0 = __half22float2(*(__half2*)&u.x);
        float2 f1 = __half22float2(*(__half2*)&u.y);
        acc.x = fmaf(f0.x, w, acc.x); acc.y = fmaf(f0.y, w, acc.y);
        acc.z = fmaf(f1.x, w, acc.z); acc.w = fmaf(f1.y, w, acc.w);
    };

    int j = beg;
    for (; j + 3 < end; j += 4) {
        int2 sw0 = __ldg(&esw[j]);
        int2 sw1 = __ldg(&esw[j + 1]);
        int2 sw2 = __ldg(&esw[j + 2]);
        int2 sw3 = __ldg(&esw[j + 3]);
        uint2 v0 = __ldg(&h2[(size_t)sw0.x * 32 + lane]);
        uint2 v1 = __ldg(&h2[(size_t)sw1.x * 32 + lane]);
        uint2 v2 = __ldg(&h2[(size_t)sw2.x * 32 + lane]);
        uint2 v3 = __ldg(&h2[(size_t)sw3.x * 32 + lane]);
        accum(v0, __int_as_float(sw0.y));
        accum(v1, __int_as_float(sw1.y));
        accum(v2, __int_as_float(sw2.y));
        accum(v3, __int_as_float(sw3.y));
    }
    for (; j < end; ++j) {
        int2 sw = __ldg(&esw[j]);
        uint2 v = __ldg(&h2[(size_t)sw.x * 32 + lane]);
        accum(v, __int_as_float(sw.y));
    }

    acc.x = fmaxf(acc.x, 0.f); acc.y = fmaxf(acc.y, 0.f);
    acc.z = fmaxf(acc.z, 0.f); acc.w = fmaxf(acc.w, 0.f);
    if (MODE == 1) {
        uint2 r = __ldg(&((const uint2*)res)[(size_t)warp * 32 + lane]);
        float2 r0 = __half22float2(*(__half2*)&r.x);
        float2 r1 = __half22float2(*(__half2*)&r.y);
        acc.x += r0.x; acc.y += r0.y; acc.z += r1.x; acc.w += r1.y;
    }

    __half2 o0 = __floats2half2_rn(acc.x, acc.y);
    __half2 o1 = __floats2half2_rn(acc.z, acc.w);
    uint2 u;
    u.x = *(uint32_t*)&o0;
    u.y = *(uint32_t*)&o1;
    *(uint2*)&out[(size_t)warp * 128 + lane * 4] = u;
}

// ---------------------------------------------------------------------------
// Final aggregation (F=40, fp32) fused with log_softmax; writes d_out.
// ---------------------------------------------------------------------------
__global__ void agg40_lsm_kernel(const float* __restrict__ h,
                                 const int* __restrict__ rowptr,
                                 const int2* __restrict__ esw,
                                 float* __restrict__ out, int n) {
    int warp = (blockIdx.x * blockDim.x + threadIdx.x) >> 5;
    int lane = threadIdx.x & 31;
    if (warp >= n) return;
    int beg = rowptr[warp];
    int end = rowptr[warp + 1];

    float a0 = 0.f, a1 = 0.f;
    for (int j = beg; j < end; ++j) {
        int2 sw = __ldg(&esw[j]);
        float w = __int_as_float(sw.y);
        const float* hp = h + (size_t)sw.x * F_OUT;
        a0 = fmaf(__ldg(&hp[lane]), w, a0);
        if (lane < 8) a1 = fmaf(__ldg(&hp[32 + lane]), w, a1);
    }

    float m = a0;
    if (lane < 8) m = fmaxf(m, a1);
#pragma unroll
    for (int o = 16; o > 0; o >>= 1)
        m = fmaxf(m, __shfl_xor_sync(0xffffffffu, m, o));

    float s = expf(a0 - m) + ((lane < 8) ? expf(a1 - m) : 0.f);
#pragma unroll
    for (int o = 16; o > 0; o >>= 1)
        s += __shfl_xor_sync(0xffffffffu, s, o);
    float lse = logf(s);

    out[(size_t)warp * F_OUT + lane] = a0 - m - lse;
    if (lane < 8)
        out[(size_t)warp * F_OUT + 32 + lane] = a1 - m - lse;
}

// ---------------------------------------------------------------------------
// Launch
// ---------------------------------------------------------------------------
extern "C" void kernel_launch(void* const* d_in, const int* in_sizes, int n_in,
                              void* d_out, int out_size) {
    const float* x   = (const float*)d_in[0];
    const int*   src = (const int*)  d_in[1];
    const int*   tgt = (const int*)  d_in[2];
    const float* ew  = (const float*)d_in[3];
    const float* W0  = (const float*)d_in[4];
    const float* b0  = (const float*)d_in[5];
    const float* W1  = (const float*)d_in[6];
    const float* b1  = (const float*)d_in[7];
    const float* W2  = (const float*)d_in[8];
    const float* b2  = (const float*)d_in[9];
    const float* W3  = (const float*)d_in[10];
    const float* b3  = (const float*)d_in[11];
    float* out = (float*)d_out;

    float* h;
    __half *hh, *act0, *act1, *act2, *xf;
    __half *w0h, *w0l, *w1h, *w1l, *w2h, *w2l, *w3h, *w3l;
    int *deg, *rowptr, *cursor;
    int2* esw;
    cudaGetSymbolAddress((void**)&h,    g_h);
    cudaGetSymbolAddress((void**)&hh,   g_hh);
    cudaGetSymbolAddress((void**)&act0, g_act0);
    cudaGetSymbolAddress((void**)&act1, g_act1);
    cudaGetSymbolAddress((void**)&act2, g_act2);
    cudaGetSymbolAddress((void**)&xf,   g_xf);
    cudaGetSymbolAddress((void**)&w0h, g_w0h);
    cudaGetSymbolAddress((void**)&w0l, g_w0l);
    cudaGetSymbolAddress((void**)&w1h, g_w1h);
    cudaGetSymbolAddress((void**)&w1l, g_w1l);
    cudaGetSymbolAddress((void**)&w2h, g_w2h);
    cudaGetSymbolAddress((void**)&w2l, g_w2l);
    cudaGetSymbolAddress((void**)&w3h, g_w3h);
    cudaGetSymbolAddress((void**)&w3l, g_w3l);
    cudaGetSymbolAddress((void**)&deg,    g_deg);
    cudaGetSymbolAddress((void**)&rowptr, g_rowptr);
    cudaGetSymbolAddress((void**)&cursor, g_cursor);
    cudaGetSymbolAddress((void**)&esw,    g_esw);

    const int M = NNODES;
    const int E = NEDGES;
    const int NTILES = (M + 127) / 128;

    // Dynamic smem: 3 stages × (A + Wh + Wl).
    // BN=128: 3 × (128*40 + 2*128*40) * 2B = 92160;  BN=64: 3 × 10240*2 = 61440.
    const int SMEM_128 = 3 * (128 * 40 + 2 * 128 * 40) * 2;
    const int SMEM_64  = 3 * (128 * 40 + 2 *  64 * 40) * 2;
    cudaFuncSetAttribute(gemm_mma_kernel<F_IN,  F_HID, 128, 1>,
                         cudaFuncAttributeMaxDynamicSharedMemorySize, SMEM_128);
    cudaFuncSetAttribute(gemm_mma_kernel<F_HID, F_HID, 128, 1>,
                         cudaFuncAttributeMaxDynamicSharedMemorySize, SMEM_128);
    cudaFuncSetAttribute(gemm_mma_kernel<F_HID, F_OUT, 64, 0>,
                         cudaFuncAttributeMaxDynamicSharedMemorySize, SMEM_64);

    const int G128 = 296;    // 2 blocks/SM (regs/smem)
    const int G64  = 296;
    const int agg_blocks = (M + 7) / 8;

    // 0: convert_x  1: convert_w_all  2: zero  3: GEMM0 (ncu slot)  4: hist ...
    {
        int n4 = M * F_IN / 4;
        convert_x_kernel<<<(n4 + 255) / 256, 256>>>(x, xf, n4);
        int tot = 128 * 256 + 128 * 128 + 128 * 128 + 64 * 128;
        convert_w_all_kernel<<<(tot + 255) / 256, 256>>>(W0, w0h, w0l, W1, w1h, w1l,
                                                         W2, w2h, w2l, W3, w3h, w3l);
    }
    zero_int_kernel<<<(M + 255) / 256, 256>>>(deg, M);

    // ---- layer 0 GEMM (fp16 out) ----
    gemm_mma_kernel<F_IN, F_HID, 128, 1><<<G128, 256, SMEM_128>>>(xf, w0h, w0l, b0, hh, M, NTILES);

    // ---- CSR build ----
    hist_kernel<<<(E + 255) / 256, 256>>>(tgt, deg, E);
    scan_kernel<<<1, 1024>>>(deg, rowptr, cursor, M);
    fill_kernel<<<(E + 255) / 256, 256>>>(src, tgt, ew, cursor, esw, E);

    // ---- layer 0 agg: act0 = relu(scatter(hh)) ----
    agg128_kernel<0><<<agg_blocks, 256>>>(hh, rowptr, esw, nullptr, act0, M);

    // ---- layer 1 ----
    gemm_mma_kernel<F_HID, F_HID, 128, 1><<<G128, 256, SMEM_128>>>(act0, w1h, w1l, b1, hh, M, NTILES);
    agg128_kernel<0><<<agg_blocks, 256>>>(hh, rowptr, esw, nullptr, act1, M);

    // ---- layer 2 (residual = act0) ----
    gemm_mma_kernel<F_HID, F_HID, 128, 1><<<G128, 256, SMEM_128>>>(act1, w2h, w2l, b2, hh, M, NTILES);
    agg128_kernel<1><<<agg_blocks, 256>>>(hh, rowptr, esw, act0, act2, M);

    // ---- layer 3 (fp32 logits path) ----
    gemm_mma_kernel<F_HID, F_OUT, 64, 0><<<G64, 256, SMEM_64>>>(act2, w3h, w3l, b3, h, M, NTILES);
    agg40_lsm_kernel<<<agg_blocks, 256>>>(h, rowptr, esw, out, M);
}

// round 15
// speedup vs baseline: 1.8041x; 1.0763x over previous
#include <cuda_runtime.h>
#include <cuda_bf16.h>
#include <cuda_fp16.h>
#include <math.h>
#include <stdint.h>

// Problem constants (fixed by the reference setup).
#define NNODES 100000
#define NEDGES 1600000
#define F_IN   256
#define F_HID  128
#define F_OUT  40

// ---------------------------------------------------------------------------
// Scratch (device globals; no cudaMalloc allowed)
// ---------------------------------------------------------------------------
__device__ float  g_h   [NNODES * F_OUT];      // fp32 GEMM out (layer 3)
__device__ __half g_hh  [NNODES * F_HID];      // fp16 GEMM out (layers 0-2)
__device__ __half g_act0[NNODES * F_HID];      // x0 (GEMM1 input + residual)
__device__ __half g_act1[NNODES * F_HID];      // x1
__device__ __half g_act2[NNODES * F_HID];      // x2
__device__ __half g_xf  [NNODES * F_IN];       // input x in fp16
// Transposed, padded fp16 weights: Wt[n][k]
__device__ __half g_w0[128 * 256];
__device__ __half g_w1[128 * 128];
__device__ __half g_w2[128 * 128];
__device__ __half g_w3[ 64 * 128];
// CSR
__device__ int  g_deg   [NNODES];
__device__ int  g_rowptr[NNODES + 1];
__device__ int  g_cursor[NNODES];
__device__ int2 g_esw   [NEDGES];

// ---------------------------------------------------------------------------
// Helpers
// ---------------------------------------------------------------------------
__device__ __forceinline__ void ldsm4(uint32_t* d, const void* p) {
    uint32_t a = (uint32_t)__cvta_generic_to_shared(p);
    asm volatile("ldmatrix.sync.aligned.m8n8.x4.shared.b16 {%0,%1,%2,%3}, [%4];\n"
                 : "=r"(d[0]), "=r"(d[1]), "=r"(d[2]), "=r"(d[3]) : "r"(a));
}

__device__ __forceinline__ void mma_f16(float* c, const uint32_t* a, const uint32_t* b) {
    asm volatile(
        "mma.sync.aligned.m16n8k16.row.col.f32.f16.f16.f32 "
        "{%0,%1,%2,%3}, {%4,%5,%6,%7}, {%8,%9}, {%0,%1,%2,%3};\n"
        : "+f"(c[0]), "+f"(c[1]), "+f"(c[2]), "+f"(c[3])
        : "r"(a[0]), "r"(a[1]), "r"(a[2]), "r"(a[3]), "r"(b[0]), "r"(b[1]));
}

__device__ __forceinline__ void cpa16(void* dst_smem, const void* src, int src_bytes) {
    uint32_t d = (uint32_t)__cvta_generic_to_shared(dst_smem);
    asm volatile("cp.async.cg.shared.global [%0], [%1], 16, %2;\n"
                 :: "r"(d), "l"(src), "r"(src_bytes));
}
__device__ __forceinline__ void cpa_commit() {
    asm volatile("cp.async.commit_group;\n");
}
template<int N>
__device__ __forceinline__ void cpa_wait() {
    asm volatile("cp.async.wait_group %0;\n" :: "n"(N));
}

// ---------------------------------------------------------------------------
// CSR build
// ---------------------------------------------------------------------------
__global__ void hist_kernel(const int* __restrict__ tgt, int* __restrict__ deg, int e) {
    int i = blockIdx.x * blockDim.x + threadIdx.x;
    if (i < e) atomicAdd(&deg[tgt[i]], 1);
}

__global__ void scan_kernel(const int* __restrict__ deg, int* __restrict__ rowptr,
                            int* __restrict__ cursor, int n) {
    __shared__ int sums[1024];
    int t = threadIdx.x;
    const int CH = (n + 1023) >> 10;
    int beg = t * CH;
    int endi = beg + CH; if (endi > n) endi = n;
    int s = 0;
    for (int i = beg; i < endi; ++i) s += deg[i];
    sums[t] = s;
    __syncthreads();
    for (int off = 1; off < 1024; off <<= 1) {
        int v = (t >= off) ? sums[t - off] : 0;
        __syncthreads();
        sums[t] += v;
        __syncthreads();
    }
    int run = (t == 0) ? 0 : sums[t - 1];
    for (int i = beg; i < endi; ++i) {
        rowptr[i] = run;
        cursor[i] = run;
        run += deg[i];
    }
    if (t == 0) rowptr[n] = sums[1023];
}

__global__ void fill_kernel(const int* __restrict__ src, const int* __restrict__ tgt,
                            const float* __restrict__ ew, int* __restrict__ cursor,
                            int2* __restrict__ esw, int e) {
    int i = blockIdx.x * blockDim.x + threadIdx.x;
    if (i < e) {
        int p = atomicAdd(&cursor[tgt[i]], 1);
        esw[p] = make_int2(src[i], __float_as_int(ew[i]));
    }
}

// ---------------------------------------------------------------------------
// Conversion kernels
// ---------------------------------------------------------------------------
__global__ void convert_x_kernel(const float* __restrict__ in,
                                 __half* __restrict__ o, int n4) {
    int i = blockIdx.x * blockDim.x + threadIdx.x;
    if (i >= n4) return;
    float4 v = ((const float4*)in)[i];
    __half2 a = __floats2half2_rn(v.x, v.y);
    __half2 b = __floats2half2_rn(v.z, v.w);
    uint2 u;
    u.x = *(uint32_t*)&a;
    u.y = *(uint32_t*)&b;
    *(uint2*)&o[(size_t)i * 4] = u;
}

// All four weights in one launch: transpose + fp16 + pad.
__global__ void convert_w_all_kernel(const float* __restrict__ W0, __half* o0,
                                     const float* __restrict__ W1, __half* o1,
                                     const float* __restrict__ W2, __half* o2,
                                     const float* __restrict__ W3, __half* o3) {
    const int S0 = 128 * 256, S1 = 128 * 128, S2 = 128 * 128, S3 = 64 * 128;
    int idx = blockIdx.x * blockDim.x + threadIdx.x;
    const float* W; __half* o; int K, N;
    if (idx < S0)                { W = W0; o = o0; K = 256; N = 128; }
    else if ((idx -= S0) < S1)   { W = W1; o = o1; K = 128; N = 128; }
    else if ((idx -= S1) < S2)   { W = W2; o = o2; K = 128; N = 128; }
    else if ((idx -= S2) < S3)   { W = W3; o = o3; K = 128; N = 40;  }
    else return;
    int n = idx / K, k = idx % K;
    float v = (n < N) ? W[(size_t)k * N + n] : 0.0f;
    o[idx] = __float2half(v);
}

// ---------------------------------------------------------------------------
// Persistent tensor-core GEMM, 3-stage cp.async ring, cross-tile prefetch.
// C = A @ W + bias.  A fp16 [M][K]; W fp16, transposed [BN][K].
// BM=128, BK=32, 256 threads (8 warps). HALF_OUT selects fp16 vs fp32 C.
// ---------------------------------------------------------------------------
template<int K, int NOUT, int BN, int HALF_OUT>
__global__ void __launch_bounds__(256)
gemm_mma_kernel(const __half* __restrict__ A,
                const __half* __restrict__ W,
                const float* __restrict__ bias,
                void* __restrict__ Cv, int M, int ntiles) {
    constexpr int BM  = 128, BK = 32;
    constexpr int BKP = BK + 8;                // 80B row stride, conflict-free LDSM
    constexpr int WARPS_N = BN / 32;           // 4 or 2
    constexpr int WARPS_M = 8 / WARPS_N;       // 2 or 4
    constexpr int MT = (BM / WARPS_M) / 16;    // 4 or 2
    constexpr int NT = 4;
    constexpr int TA = BM * BKP;
    constexpr int TW = BN * BKP;
    constexpr int STAGE = TA + TW;             // A, W
    constexpr int NKI = K / BK;

    extern __shared__ __align__(16) __half sm[];

    const int tid  = threadIdx.x;
    const int wid  = tid >> 5;
    const int lane = tid & 31;
    const int wm   = (wid / WARPS_N) * (MT * 16);
    const int wn   = (wid % WARPS_N) * 32;

    auto load_stage = [&](int s, int row0, int kk) {
        __half* bA = sm + s * STAGE;
        __half* bW = bA + TA;
#pragma unroll
        for (int t = tid; t < BM * 4; t += 256) {
            int r = t >> 2, c = (t & 3) * 8;
            int grow = row0 + r;
            size_t ridx = (grow < M) ? (size_t)grow : 0;
            int nb = (grow < M) ? 16 : 0;
            cpa16(&bA[r * BKP + c], &A[ridx * K + kk + c], nb);
        }
#pragma unroll
        for (int t = tid; t < BN * 4; t += 256) {
            int r = t >> 2, c = (t & 3) * 8;
            cpa16(&bW[r * BKP + c], &W[(size_t)r * K + kk + c], 16);
        }
    };

    int ct = blockIdx.x;
    if (ct >= ntiles) return;

    // load cursor
    int lt = ct, lk = 0;
    auto adv = [&]() { if (++lk == NKI) { lk = 0; lt += gridDim.x; } };

    // preload stages 0, 1
    load_stage(0, lt * BM, lk * BK); cpa_commit(); adv();
    if (lt < ntiles) { load_stage(1, lt * BM, lk * BK); adv(); }
    cpa_commit();

    int sbuf = 2, cbuf = 0;
    const int rbase = lane >> 2;
    const int cbase = (lane & 3) * 2;

    for (int ctile = ct; ctile < ntiles; ctile += gridDim.x) {
        float acc[MT][NT][4];
#pragma unroll
        for (int i = 0; i < MT; ++i)
#pragma unroll
            for (int j = 0; j < NT; ++j)
#pragma unroll
                for (int q = 0; q < 4; ++q) acc[i][j][q] = 0.0f;

        for (int ck = 0; ck < NKI; ++ck) {
            if (lt < ntiles) { load_stage(sbuf, lt * BM, lk * BK); adv(); }
            cpa_commit();
            cpa_wait<2>();           // oldest (cbuf's) group complete
            __syncthreads();

            const __half* bA = sm + cbuf * STAGE;
            const __half* bW = bA + TA;

#pragma unroll
            for (int ks = 0; ks < BK; ks += 16) {
                uint32_t af[MT][4];
#pragma unroll
                for (int mt = 0; mt < MT; ++mt) {
                    int r = wm + mt * 16 + (lane & 15);
                    int c = ks + ((lane >> 4) << 3);
                    ldsm4(af[mt], &bA[r * BKP + c]);
                }
                uint32_t bw[NT][2];
#pragma unroll
                for (int np = 0; np < NT / 2; ++np) {
                    int n = wn + np * 16 + (lane & 7) + ((lane >> 4) << 3);
                    int c = ks + (((lane >> 3) & 1) << 3);
                    uint32_t t4[4];
                    ldsm4(t4, &bW[n * BKP + c]);
                    bw[2 * np][0] = t4[0]; bw[2 * np][1] = t4[1];
                    bw[2 * np + 1][0] = t4[2]; bw[2 * np + 1][1] = t4[3];
                }
#pragma unroll
                for (int mt = 0; mt < MT; ++mt)
#pragma unroll
                    for (int nt = 0; nt < NT; ++nt)
                        mma_f16(acc[mt][nt], af[mt], bw[nt]);
            }
            __syncthreads();
            sbuf = (sbuf == 2) ? 0 : sbuf + 1;
            cbuf = (cbuf == 2) ? 0 : cbuf + 1;
        }

        // epilogue (registers only; overlaps in-flight next-tile loads)
        int row0 = ctile * BM;
#pragma unroll
        for (int mt = 0; mt < MT; ++mt)
#pragma unroll
            for (int nt = 0; nt < NT; ++nt) {
                int col = wn + nt * 8 + cbase;
                if (col >= NOUT) continue;
                float bx = bias[col], by = bias[col + 1];
#pragma unroll
                for (int h = 0; h < 2; ++h) {
                    int row = row0 + wm + mt * 16 + rbase + h * 8;
                    if (row < M) {
                        float cx = acc[mt][nt][h * 2 + 0] + bx;
                        float cy = acc[mt][nt][h * 2 + 1] + by;
                        if (HALF_OUT) {
                            __half2 v = __floats2half2_rn(cx, cy);
                            *(__half2*)&((__half*)Cv)[(size_t)row * NOUT + col] = v;
                        } else {
                            float2 v = make_float2(cx, cy);
                            *(float2*)&((float*)Cv)[(size_t)row * NOUT + col] = v;
                        }
                    }
                }
            }
    }
}

// ---------------------------------------------------------------------------
// Aggregation (gather-CSR) over fp16 messages, F=128, warp per node.
// fp32 accumulate; writes fp16 activation. MODE 1 adds fp16 residual.
// ---------------------------------------------------------------------------
template<int MODE>
__global__ void agg128_kernel(const __half* __restrict__ h,
                              const int* __restrict__ rowptr,
                              const int2* __restrict__ esw,
                              const __half* __restrict__ res,
                              __half* __restrict__ out, int n) {
    int warp = (blockIdx.x * blockDim.x + threadIdx.x) >> 5;
    int lane = threadIdx.x & 31;
    if (warp >= n) return;
    int beg = rowptr[warp];
    int end = rowptr[warp + 1];

    const uint2* h2 = (const uint2*)h;      // 4 halves per uint2; 32 per row
    float4 acc = make_float4(0.f, 0.f, 0.f, 0.f);

    auto accum = [&](uint2 u, float w) {
        float2 f0 = __half22float2(*(__half2*)&u.x);
        float2 f1 = __half22float2(*(__half2*)&u.y);
        acc.x = fmaf(f0.x, w, acc.x); acc.y = fmaf(f0.y, w, acc.y);
        acc.z = fmaf(f1.x, w, acc.z); acc.w = fmaf(f1.y, w, acc.w);
    };

    int j = beg;
    for (; j + 3 < end; j += 4) {
        int2 sw0 = __ldg(&esw[j]);
        int2 sw1 = __ldg(&esw[j + 1]);
        int2 sw2 = __ldg(&esw[j + 2]);
        int2 sw3 = __ldg(&esw[j + 3]);
        uint2 v0 = __ldg(&h2[(size_t)sw0.x * 32 + lane]);
        uint2 v1 = __ldg(&h2[(size_t)sw1.x * 32 + lane]);
        uint2 v2 = __ldg(&h2[(size_t)sw2.x * 32 + lane]);
        uint2 v3 = __ldg(&h2[(size_t)sw3.x * 32 + lane]);
        accum(v0, __int_as_float(sw0.y));
        accum(v1, __int_as_float(sw1.y));
        accum(v2, __int_as_float(sw2.y));
        accum(v3, __int_as_float(sw3.y));
    }
    for (; j < end; ++j) {
        int2 sw = __ldg(&esw[j]);
        uint2 v = __ldg(&h2[(size_t)sw.x * 32 + lane]);
        accum(v, __int_as_float(sw.y));
    }

    acc.x = fmaxf(acc.x, 0.f); acc.y = fmaxf(acc.y, 0.f);
    acc.z = fmaxf(acc.z, 0.f); acc.w = fmaxf(acc.w, 0.f);
    if (MODE == 1) {
        uint2 r = __ldg(&((const uint2*)res)[(size_t)warp * 32 + lane]);
        float2 r0 = __half22float2(*(__half2*)&r.x);
        float2 r1 = __half22float2(*(__half2*)&r.y);
        acc.x += r0.x; acc.y += r0.y; acc.z += r1.x; acc.w += r1.y;
    }

    __half2 o0 = __floats2half2_rn(acc.x, acc.y);
    __half2 o1 = __floats2half2_rn(acc.z, acc.w);
    uint2 u;
    u.x = *(uint32_t*)&o0;
    u.y = *(uint32_t*)&o1;
    *(uint2*)&out[(size_t)warp * 128 + lane * 4] = u;
}

// ---------------------------------------------------------------------------
// Final aggregation (F=40, fp32) fused with log_softmax; writes d_out.
// ---------------------------------------------------------------------------
__global__ void agg40_lsm_kernel(const float* __restrict__ h,
                                 const int* __restrict__ rowptr,
                                 const int2* __restrict__ esw,
                                 float* __restrict__ out, int n) {
    int warp = (blockIdx.x * blockDim.x + threadIdx.x) >> 5;
    int lane = threadIdx.x & 31;
    if (warp >= n) return;
    int beg = rowptr[warp];
    int end = rowptr[warp + 1];

    float a0 = 0.f, a1 = 0.f;
    for (int j = beg; j < end; ++j) {
        int2 sw = __ldg(&esw[j]);
        float w = __int_as_float(sw.y);
        const float* hp = h + (size_t)sw.x * F_OUT;
        a0 = fmaf(__ldg(&hp[lane]), w, a0);
        if (lane < 8) a1 = fmaf(__ldg(&hp[32 + lane]), w, a1);
    }

    float m = a0;
    if (lane < 8) m = fmaxf(m, a1);
#pragma unroll
    for (int o = 16; o > 0; o >>= 1)
        m = fmaxf(m, __shfl_xor_sync(0xffffffffu, m, o));

    float s = expf(a0 - m) + ((lane < 8) ? expf(a1 - m) : 0.f);
#pragma unroll
    for (int o = 16; o > 0; o >>= 1)
        s += __shfl_xor_sync(0xffffffffu, s, o);
    float lse = logf(s);

    out[(size_t)warp * F_OUT + lane] = a0 - m - lse;
    if (lane < 8)
        out[(size_t)warp * F_OUT + 32 + lane] = a1 - m - lse;
}

// ---------------------------------------------------------------------------
// Launch
// ---------------------------------------------------------------------------
extern "C" void kernel_launch(void* const* d_in, const int* in_sizes, int n_in,
                              void* d_out, int out_size) {
    const float* x   = (const float*)d_in[0];
    const int*   src = (const int*)  d_in[1];
    const int*   tgt = (const int*)  d_in[2];
    const float* ew  = (const float*)d_in[3];
    const float* W0  = (const float*)d_in[4];
    const float* b0  = (const float*)d_in[5];
    const float* W1  = (const float*)d_in[6];
    const float* b1  = (const float*)d_in[7];
    const float* W2  = (const float*)d_in[8];
    const float* b2  = (const float*)d_in[9];
    const float* W3  = (const float*)d_in[10];
    const float* b3  = (const float*)d_in[11];
    float* out = (float*)d_out;

    float* h;
    __half *hh, *act0, *act1, *act2, *xf;
    __half *w0, *w1, *w2, *w3;
    int *deg, *rowptr, *cursor;
    int2* esw;
    cudaGetSymbolAddress((void**)&h,    g_h);
    cudaGetSymbolAddress((void**)&hh,   g_hh);
    cudaGetSymbolAddress((void**)&act0, g_act0);
    cudaGetSymbolAddress((void**)&act1, g_act1);
    cudaGetSymbolAddress((void**)&act2, g_act2);
    cudaGetSymbolAddress((void**)&xf,   g_xf);
    cudaGetSymbolAddress((void**)&w0,   g_w0);
    cudaGetSymbolAddress((void**)&w1,   g_w1);
    cudaGetSymbolAddress((void**)&w2,   g_w2);
    cudaGetSymbolAddress((void**)&w3,   g_w3);
    cudaGetSymbolAddress((void**)&deg,    g_deg);
    cudaGetSymbolAddress((void**)&rowptr, g_rowptr);
    cudaGetSymbolAddress((void**)&cursor, g_cursor);
    cudaGetSymbolAddress((void**)&esw,    g_esw);

    const int M = NNODES;
    const int E = NEDGES;
    const int NTILES = (M + 127) / 128;

    // Dynamic smem: 3 stages × (A + W).
    // BN=128: 3 × (128*40 + 128*40) × 2B = 61440;  BN=64: 46080.
    const int SMEM_128 = 3 * (128 * 40 + 128 * 40) * 2;
    const int SMEM_64  = 3 * (128 * 40 +  64 * 40) * 2;
    cudaFuncSetAttribute(gemm_mma_kernel<F_IN,  F_HID, 128, 1>,
                         cudaFuncAttributeMaxDynamicSharedMemorySize, SMEM_128);
    cudaFuncSetAttribute(gemm_mma_kernel<F_HID, F_HID, 128, 1>,
                         cudaFuncAttributeMaxDynamicSharedMemorySize, SMEM_128);
    cudaFuncSetAttribute(gemm_mma_kernel<F_HID, F_OUT, 64, 0>,
                         cudaFuncAttributeMaxDynamicSharedMemorySize, SMEM_64);

    const int G128 = 296;
    const int G64  = 296;
    const int agg_blocks = (M + 7) / 8;

    // conversions + deg zeroing (memset node; graph-capturable)
    {
        int n4 = M * F_IN / 4;
        convert_x_kernel<<<(n4 + 255) / 256, 256>>>(x, xf, n4);
        int tot = 128 * 256 + 128 * 128 + 128 * 128 + 64 * 128;
        convert_w_all_kernel<<<(tot + 255) / 256, 256>>>(W0, w0, W1, w1, W2, w2, W3, w3);
    }
    cudaMemsetAsync(deg, 0, M * sizeof(int));

    // ---- layer 0 GEMM (fp16 out) ----
    gemm_mma_kernel<F_IN, F_HID, 128, 1><<<G128, 256, SMEM_128>>>(xf, w0, b0, hh, M, NTILES);

    // ---- CSR build ----
    hist_kernel<<<(E + 255) / 256, 256>>>(tgt, deg, E);
    scan_kernel<<<1, 1024>>>(deg, rowptr, cursor, M);
    fill_kernel<<<(E + 255) / 256, 256>>>(src, tgt, ew, cursor, esw, E);

    // ---- layer 0 agg: act0 = relu(scatter(hh)) ----
    agg128_kernel<0><<<agg_blocks, 256>>>(hh, rowptr, esw, nullptr, act0, M);

    // ---- layer 1 ----
    gemm_mma_kernel<F_HID, F_HID, 128, 1><<<G128, 256, SMEM_128>>>(act0, w1, b1, hh, M, NTILES);
    agg128_kernel<0><<<agg_blocks, 256>>>(hh, rowptr, esw, nullptr, act1, M);

    // ---- layer 2 (residual = act0) ----
    gemm_mma_kernel<F_HID, F_HID, 128, 1><<<G128, 256, SMEM_128>>>(act1, w2, b2, hh, M, NTILES);
    agg128_kernel<1><<<agg_blocks, 256>>>(hh, rowptr, esw, act0, act2, M);

    // ---- layer 3 (fp32 logits path) ----
    gemm_mma_kernel<F_HID, F_OUT, 64, 0><<<G64, 256, SMEM_64>>>(act2, w3, b3, h, M, NTILES);
    agg40_lsm_kernel<<<agg_blocks, 256>>>(h, rowptr, esw, out, M);
}

// round 17
// speedup vs baseline: 2.6561x; 1.4722x over previous
#include <cuda_runtime.h>
#include <cuda_bf16.h>
#include <cuda_fp16.h>
#include <math.h>
#include <stdint.h>

// Problem constants (fixed by the reference setup).
#define NNODES 100000
#define NEDGES 1600000
#define F_IN   256
#define F_HID  128
#define F_OUT  40

// ---------------------------------------------------------------------------
// Scratch (device globals; no cudaMalloc allowed)
// ---------------------------------------------------------------------------
__device__ float  g_h   [NNODES * F_OUT];      // fp32 GEMM out (layer 3)
__device__ __half g_hh  [NNODES * F_HID];      // fp16 GEMM out (layers 0-2)
__device__ __half g_act0[NNODES * F_HID];      // x0 (GEMM1 input + residual)
__device__ __half g_act1[NNODES * F_HID];      // x1
__device__ __half g_act2[NNODES * F_HID];      // x2
__device__ __half g_xf  [NNODES * F_IN];       // input x in fp16
// Transposed, padded fp16 weights: Wt[n][k]
__device__ __half g_w0[128 * 256];
__device__ __half g_w1[128 * 128];
__device__ __half g_w2[128 * 128];
__device__ __half g_w3[ 64 * 128];
// CSR
__device__ int  g_deg   [NNODES];
__device__ int  g_rowptr[NNODES + 1];
__device__ int  g_cursor[NNODES];
__device__ int  g_bsum  [128];
__device__ int  g_boff  [129];
__device__ int2 g_esw   [NEDGES];

// ---------------------------------------------------------------------------
// Helpers
// ---------------------------------------------------------------------------
__device__ __forceinline__ void ldsm4(uint32_t* d, const void* p) {
    uint32_t a = (uint32_t)__cvta_generic_to_shared(p);
    asm volatile("ldmatrix.sync.aligned.m8n8.x4.shared.b16 {%0,%1,%2,%3}, [%4];\n"
                 : "=r"(d[0]), "=r"(d[1]), "=r"(d[2]), "=r"(d[3]) : "r"(a));
}

__device__ __forceinline__ void mma_f16(float* c, const uint32_t* a, const uint32_t* b) {
    asm volatile(
        "mma.sync.aligned.m16n8k16.row.col.f32.f16.f16.f32 "
        "{%0,%1,%2,%3}, {%4,%5,%6,%7}, {%8,%9}, {%0,%1,%2,%3};\n"
        : "+f"(c[0]), "+f"(c[1]), "+f"(c[2]), "+f"(c[3])
        : "r"(a[0]), "r"(a[1]), "r"(a[2]), "r"(a[3]), "r"(b[0]), "r"(b[1]));
}

__device__ __forceinline__ void cpa16(void* dst_smem, const void* src, int src_bytes) {
    uint32_t d = (uint32_t)__cvta_generic_to_shared(dst_smem);
    asm volatile("cp.async.cg.shared.global [%0], [%1], 16, %2;\n"
                 :: "r"(d), "l"(src), "r"(src_bytes));
}
__device__ __forceinline__ void cpa_commit() {
    asm volatile("cp.async.commit_group;\n");
}
template<int N>
__device__ __forceinline__ void cpa_wait() {
    asm volatile("cp.async.wait_group %0;\n" :: "n"(N));
}

// ---------------------------------------------------------------------------
// CSR build
// ---------------------------------------------------------------------------
__global__ void hist_kernel(const int* __restrict__ tgt, int* __restrict__ deg, int e) {
    int i = blockIdx.x * blockDim.x + threadIdx.x;
    if (i < e) atomicAdd(&deg[tgt[i]], 1);
}

// 3-phase multi-block exclusive scan over deg[n].
__global__ void scan_bsum_kernel(const int* __restrict__ deg, int* __restrict__ bsum, int n) {
    __shared__ int red[1024];
    int t = threadIdx.x;
    int i = blockIdx.x * 1024 + t;
    red[t] = (i < n) ? deg[i] : 0;
    __syncthreads();
#pragma unroll
    for (int o = 512; o > 0; o >>= 1) {
        if (t < o) red[t] += red[t + o];
        __syncthreads();
    }
    if (t == 0) bsum[blockIdx.x] = red[0];
}

__global__ void scan_boff_kernel(const int* __restrict__ bsum, int* __restrict__ boff, int nb) {
    __shared__ int s[128];
    int t = threadIdx.x;
    s[t] = (t < nb) ? bsum[t] : 0;
    __syncthreads();
#pragma unroll
    for (int o = 1; o < 128; o <<= 1) {
        int v = (t >= o) ? s[t - o] : 0;
        __syncthreads();
        s[t] += v;
        __syncthreads();
    }
    if (t < nb) boff[t] = (t == 0) ? 0 : s[t - 1];
}

__global__ void scan_write_kernel(const int* __restrict__ deg, const int* __restrict__ boff,
                                  int* __restrict__ rowptr, int* __restrict__ cursor, int n) {
    __shared__ int s[1024];
    int t = threadIdx.x;
    int i = blockIdx.x * 1024 + t;
    int v = (i < n) ? deg[i] : 0;
    s[t] = v;
    __syncthreads();
#pragma unroll
    for (int o = 1; o < 1024; o <<= 1) {
        int u = (t >= o) ? s[t - o] : 0;
        __syncthreads();
        s[t] += u;
        __syncthreads();
    }
    int excl = s[t] - v + boff[blockIdx.x];
    if (i < n) { rowptr[i] = excl; cursor[i] = excl; }
    if (i == n - 1) rowptr[n] = excl + v;
}

__global__ void fill_kernel(const int* __restrict__ src, const int* __restrict__ tgt,
                            const float* __restrict__ ew, int* __restrict__ cursor,
                            int2* __restrict__ esw, int e) {
    int i = blockIdx.x * blockDim.x + threadIdx.x;
    if (i < e) {
        int p = atomicAdd(&cursor[tgt[i]], 1);
        esw[p] = make_int2(src[i], __float_as_int(ew[i]));
    }
}

// ---------------------------------------------------------------------------
// Conversion kernels
// ---------------------------------------------------------------------------
__global__ void convert_x_kernel(const float* __restrict__ in,
                                 __half* __restrict__ o, int n4) {
    int i = blockIdx.x * blockDim.x + threadIdx.x;
    if (i >= n4) return;
    float4 v = ((const float4*)in)[i];
    __half2 a = __floats2half2_rn(v.x, v.y);
    __half2 b = __floats2half2_rn(v.z, v.w);
    uint2 u;
    u.x = *(uint32_t*)&a;
    u.y = *(uint32_t*)&b;
    *(uint2*)&o[(size_t)i * 4] = u;
}

// All four weights in one launch: transpose + fp16 + pad.
__global__ void convert_w_all_kernel(const float* __restrict__ W0, __half* o0,
                                     const float* __restrict__ W1, __half* o1,
                                     const float* __restrict__ W2, __half* o2,
                                     const float* __restrict__ W3, __half* o3) {
    const int S0 = 128 * 256, S1 = 128 * 128, S2 = 128 * 128, S3 = 64 * 128;
    int idx = blockIdx.x * blockDim.x + threadIdx.x;
    const float* W; __half* o; int K, N;
    if (idx < S0)                { W = W0; o = o0; K = 256; N = 128; }
    else if ((idx -= S0) < S1)   { W = W1; o = o1; K = 128; N = 128; }
    else if ((idx -= S1) < S2)   { W = W2; o = o2; K = 128; N = 128; }
    else if ((idx -= S2) < S3)   { W = W3; o = o3; K = 128; N = 40;  }
    else return;
    int n = idx / K, k = idx % K;
    float v = (n < N) ? W[(size_t)k * N + n] : 0.0f;
    o[idx] = __float2half(v);
}

// ---------------------------------------------------------------------------
// Persistent tensor-core GEMM, 3-stage cp.async ring, cross-tile prefetch.
// C = A @ W + bias.  A fp16 [M][K]; W fp16, transposed [BN][K].
// BM=128, BK=32, 256 threads (8 warps). HALF_OUT selects fp16 vs fp32 C.
// ---------------------------------------------------------------------------
template<int K, int NOUT, int BN, int HALF_OUT>
__global__ void __launch_bounds__(256)
gemm_mma_kernel(const __half* __restrict__ A,
                const __half* __restrict__ W,
                const float* __restrict__ bias,
                void* __restrict__ Cv, int M, int ntiles) {
    constexpr int BM  = 128, BK = 32;
    constexpr int BKP = BK + 8;                // 80B row stride, conflict-free LDSM
    constexpr int WARPS_N = BN / 32;           // 4 or 2
    constexpr int WARPS_M = 8 / WARPS_N;       // 2 or 4
    constexpr int MT = (BM / WARPS_M) / 16;    // 4 or 2
    constexpr int NT = 4;
    constexpr int TA = BM * BKP;
    constexpr int TW = BN * BKP;
    constexpr int STAGE = TA + TW;             // A, W
    constexpr int NKI = K / BK;

    extern __shared__ __align__(16) __half sm[];

    const int tid  = threadIdx.x;
    const int wid  = tid >> 5;
    const int lane = tid & 31;
    const int wm   = (wid / WARPS_N) * (MT * 16);
    const int wn   = (wid % WARPS_N) * 32;

    auto load_stage = [&](int s, int row0, int kk) {
        __half* bA = sm + s * STAGE;
        __half* bW = bA + TA;
#pragma unroll
        for (int t = tid; t < BM * 4; t += 256) {
            int r = t >> 2, c = (t & 3) * 8;
            int grow = row0 + r;
            size_t ridx = (grow < M) ? (size_t)grow : 0;
            int nb = (grow < M) ? 16 : 0;
            cpa16(&bA[r * BKP + c], &A[ridx * K + kk + c], nb);
        }
#pragma unroll
        for (int t = tid; t < BN * 4; t += 256) {
            int r = t >> 2, c = (t & 3) * 8;
            cpa16(&bW[r * BKP + c], &W[(size_t)r * K + kk + c], 16);
        }
    };

    int ct = blockIdx.x;
    if (ct >= ntiles) return;

    // load cursor
    int lt = ct, lk = 0;
    auto adv = [&]() { if (++lk == NKI) { lk = 0; lt += gridDim.x; } };

    // preload stages 0, 1
    load_stage(0, lt * BM, lk * BK); cpa_commit(); adv();
    if (lt < ntiles) { load_stage(1, lt * BM, lk * BK); adv(); }
    cpa_commit();

    int sbuf = 2, cbuf = 0;
    const int rbase = lane >> 2;
    const int cbase = (lane & 3) * 2;

    for (int ctile = ct; ctile < ntiles; ctile += gridDim.x) {
        float acc[MT][NT][4];
#pragma unroll
        for (int i = 0; i < MT; ++i)
#pragma unroll
            for (int j = 0; j < NT; ++j)
#pragma unroll
                for (int q = 0; q < 4; ++q) acc[i][j][q] = 0.0f;

        for (int ck = 0; ck < NKI; ++ck) {
            if (lt < ntiles) { load_stage(sbuf, lt * BM, lk * BK); adv(); }
            cpa_commit();
            cpa_wait<2>();           // oldest (cbuf's) group complete
            __syncthreads();

            const __half* bA = sm + cbuf * STAGE;
            const __half* bW = bA + TA;

#pragma unroll
            for (int ks = 0; ks < BK; ks += 16) {
                uint32_t af[MT][4];
#pragma unroll
                for (int mt = 0; mt < MT; ++mt) {
                    int r = wm + mt * 16 + (lane & 15);
                    int c = ks + ((lane >> 4) << 3);
                    ldsm4(af[mt], &bA[r * BKP + c]);
                }
                uint32_t bw[NT][2];
#pragma unroll
                for (int np = 0; np < NT / 2; ++np) {
                    int n = wn + np * 16 + (lane & 7) + ((lane >> 4) << 3);
                    int c = ks + (((lane >> 3) & 1) << 3);
                    uint32_t t4[4];
                    ldsm4(t4, &bW[n * BKP + c]);
                    bw[2 * np][0] = t4[0]; bw[2 * np][1] = t4[1];
                    bw[2 * np + 1][0] = t4[2]; bw[2 * np + 1][1] = t4[3];
                }
#pragma unroll
                for (int mt = 0; mt < MT; ++mt)
#pragma unroll
                    for (int nt = 0; nt < NT; ++nt)
                        mma_f16(acc[mt][nt], af[mt], bw[nt]);
            }
            __syncthreads();
            sbuf = (sbuf == 2) ? 0 : sbuf + 1;
            cbuf = (cbuf == 2) ? 0 : cbuf + 1;
        }

        // epilogue (registers only; overlaps in-flight next-tile loads)
        int row0 = ctile * BM;
#pragma unroll
        for (int mt = 0; mt < MT; ++mt)
#pragma unroll
            for (int nt = 0; nt < NT; ++nt) {
                int col = wn + nt * 8 + cbase;
                if (col >= NOUT) continue;
                float bx = bias[col], by = bias[col + 1];
#pragma unroll
                for (int h = 0; h < 2; ++h) {
                    int row = row0 + wm + mt * 16 + rbase + h * 8;
                    if (row < M) {
                        float cx = acc[mt][nt][h * 2 + 0] + bx;
                        float cy = acc[mt][nt][h * 2 + 1] + by;
                        if (HALF_OUT) {
                            __half2 v = __floats2half2_rn(cx, cy);
                            *(__half2*)&((__half*)Cv)[(size_t)row * NOUT + col] = v;
                        } else {
                            float2 v = make_float2(cx, cy);
                            *(float2*)&((float*)Cv)[(size_t)row * NOUT + col] = v;
                        }
                    }
                }
            }
    }
}

// ---------------------------------------------------------------------------
// Aggregation (gather-CSR) over fp16 messages, F=128, warp per node.
// fp32 accumulate; writes fp16 activation. MODE 1 adds fp16 residual.
// ---------------------------------------------------------------------------
template<int MODE>
__global__ void agg128_kernel(const __half* __restrict__ h,
                              const int* __restrict__ rowptr,
                              const int2* __restrict__ esw,
                              const __half* __restrict__ res,
                              __half* __restrict__ out, int n) {
    int warp = (blockIdx.x * blockDim.x + threadIdx.x) >> 5;
    int lane = threadIdx.x & 31;
    if (warp >= n) return;
    int beg = rowptr[warp];
    int end = rowptr[warp + 1];

    const uint2* h2 = (const uint2*)h;      // 4 halves per uint2; 32 per row
    float4 acc = make_float4(0.f, 0.f, 0.f, 0.f);

    auto accum = [&](uint2 u, float w) {
        float2 f0 = __half22float2(*(__half2*)&u.x);
        float2 f1 = __half22float2(*(__half2*)&u.y);
        acc.x = fmaf(f0.x, w, acc.x); acc.y = fmaf(f0.y, w, acc.y);
        acc.z = fmaf(f1.x, w, acc.z); acc.w = fmaf(f1.y, w, acc.w);
    };

    int j = beg;
    for (; j + 3 < end; j += 4) {
        int2 sw0 = __ldg(&esw[j]);
        int2 sw1 = __ldg(&esw[j + 1]);
        int2 sw2 = __ldg(&esw[j + 2]);
        int2 sw3 = __ldg(&esw[j + 3]);
        uint2 v0 = __ldg(&h2[(size_t)sw0.x * 32 + lane]);
        uint2 v1 = __ldg(&h2[(size_t)sw1.x * 32 + lane]);
        uint2 v2 = __ldg(&h2[(size_t)sw2.x * 32 + lane]);
        uint2 v3 = __ldg(&h2[(size_t)sw3.x * 32 + lane]);
        accum(v0, __int_as_float(sw0.y));
        accum(v1, __int_as_float(sw1.y));
        accum(v2, __int_as_float(sw2.y));
        accum(v3, __int_as_float(sw3.y));
    }
    for (; j < end; ++j) {
        int2 sw = __ldg(&esw[j]);
        uint2 v = __ldg(&h2[(size_t)sw.x * 32 + lane]);
        accum(v, __int_as_float(sw.y));
    }

    acc.x = fmaxf(acc.x, 0.f); acc.y = fmaxf(acc.y, 0.f);
    acc.z = fmaxf(acc.z, 0.f); acc.w = fmaxf(acc.w, 0.f);
    if (MODE == 1) {
        uint2 r = __ldg(&((const uint2*)res)[(size_t)warp * 32 + lane]);
        float2 r0 = __half22float2(*(__half2*)&r.x);
        float2 r1 = __half22float2(*(__half2*)&r.y);
        acc.x += r0.x; acc.y += r0.y; acc.z += r1.x; acc.w += r1.y;
    }

    __half2 o0 = __floats2half2_rn(acc.x, acc.y);
    __half2 o1 = __floats2half2_rn(acc.z, acc.w);
    uint2 u;
    u.x = *(uint32_t*)&o0;
    u.y = *(uint32_t*)&o1;
    *(uint2*)&out[(size_t)warp * 128 + lane * 4] = u;
}

// ---------------------------------------------------------------------------
// Final aggregation (F=40, fp32) fused with log_softmax; writes d_out.
// ---------------------------------------------------------------------------
__global__ void agg40_lsm_kernel(const float* __restrict__ h,
                                 const int* __restrict__ rowptr,
                                 const int2* __restrict__ esw,
                                 float* __restrict__ out, int n) {
    int warp = (blockIdx.x * blockDim.x + threadIdx.x) >> 5;
    int lane = threadIdx.x & 31;
    if (warp >= n) return;
    int beg = rowptr[warp];
    int end = rowptr[warp + 1];

    float a0 = 0.f, a1 = 0.f;
    for (int j = beg; j < end; ++j) {
        int2 sw = __ldg(&esw[j]);
        float w = __int_as_float(sw.y);
        const float* hp = h + (size_t)sw.x * F_OUT;
        a0 = fmaf(__ldg(&hp[lane]), w, a0);
        if (lane < 8) a1 = fmaf(__ldg(&hp[32 + lane]), w, a1);
    }

    float m = a0;
    if (lane < 8) m = fmaxf(m, a1);
#pragma unroll
    for (int o = 16; o > 0; o >>= 1)
        m = fmaxf(m, __shfl_xor_sync(0xffffffffu, m, o));

    float s = expf(a0 - m) + ((lane < 8) ? expf(a1 - m) : 0.f);
#pragma unroll
    for (int o = 16; o > 0; o >>= 1)
        s += __shfl_xor_sync(0xffffffffu, s, o);
    float lse = logf(s);

    out[(size_t)warp * F_OUT + lane] = a0 - m - lse;
    if (lane < 8)
        out[(size_t)warp * F_OUT + 32 + lane] = a1 - m - lse;
}

// ---------------------------------------------------------------------------
// Launch — CSR build forked onto a side stream, overlapping convert+GEMM0.
// ---------------------------------------------------------------------------
extern "C" void kernel_launch(void* const* d_in, const int* in_sizes, int n_in,
                              void* d_out, int out_size) {
    const float* x   = (const float*)d_in[0];
    const int*   src = (const int*)  d_in[1];
    const int*   tgt = (const int*)  d_in[2];
    const float* ew  = (const float*)d_in[3];
    const float* W0  = (const float*)d_in[4];
    const float* b0  = (const float*)d_in[5];
    const float* W1  = (const float*)d_in[6];
    const float* b1  = (const float*)d_in[7];
    const float* W2  = (const float*)d_in[8];
    const float* b2  = (const float*)d_in[9];
    const float* W3  = (const float*)d_in[10];
    const float* b3  = (const float*)d_in[11];
    float* out = (float*)d_out;

    float* h;
    __half *hh, *act0, *act1, *act2, *xf;
    __half *w0, *w1, *w2, *w3;
    int *deg, *rowptr, *cursor, *bsum, *boff;
    int2* esw;
    cudaGetSymbolAddress((void**)&h,    g_h);
    cudaGetSymbolAddress((void**)&hh,   g_hh);
    cudaGetSymbolAddress((void**)&act0, g_act0);
    cudaGetSymbolAddress((void**)&act1, g_act1);
    cudaGetSymbolAddress((void**)&act2, g_act2);
    cudaGetSymbolAddress((void**)&xf,   g_xf);
    cudaGetSymbolAddress((void**)&w0,   g_w0);
    cudaGetSymbolAddress((void**)&w1,   g_w1);
    cudaGetSymbolAddress((void**)&w2,   g_w2);
    cudaGetSymbolAddress((void**)&w3,   g_w3);
    cudaGetSymbolAddress((void**)&deg,    g_deg);
    cudaGetSymbolAddress((void**)&rowptr, g_rowptr);
    cudaGetSymbolAddress((void**)&cursor, g_cursor);
    cudaGetSymbolAddress((void**)&bsum,   g_bsum);
    cudaGetSymbolAddress((void**)&boff,   g_boff);
    cudaGetSymbolAddress((void**)&esw,    g_esw);

    const int M = NNODES;
    const int E = NEDGES;
    const int NTILES = (M + 127) / 128;
    const int NB = (M + 1023) / 1024;          // 98 scan blocks

    // Dynamic smem: 3 stages × (A + W).
    const int SMEM_128 = 3 * (128 * 40 + 128 * 40) * 2;   // 61440
    const int SMEM_64  = 3 * (128 * 40 +  64 * 40) * 2;   // 46080
    cudaFuncSetAttribute(gemm_mma_kernel<F_IN,  F_HID, 128, 1>,
                         cudaFuncAttributeMaxDynamicSharedMemorySize, SMEM_128);
    cudaFuncSetAttribute(gemm_mma_kernel<F_HID, F_HID, 128, 1>,
                         cudaFuncAttributeMaxDynamicSharedMemorySize, SMEM_128);
    cudaFuncSetAttribute(gemm_mma_kernel<F_HID, F_OUT, 64, 0>,
                         cudaFuncAttributeMaxDynamicSharedMemorySize, SMEM_64);

    const int G128 = 296;
    const int G64  = 296;
    const int agg_blocks = (M + 7) / 8;

    // Static side stream + events (host objects only; created once, reused;
    // never destroyed so captured graph references stay valid).
    static cudaStream_t s_side = nullptr;
    static cudaEvent_t  e_fork = nullptr, e_join = nullptr;
    if (!s_side) {
        cudaStreamCreateWithFlags(&s_side, cudaStreamNonBlocking);
        cudaEventCreateWithFlags(&e_fork, cudaEventDisableTiming);
        cudaEventCreateWithFlags(&e_join, cudaEventDisableTiming);
    }

    // ---- fork: CSR build on side stream ----
    cudaEventRecord(e_fork, 0);
    cudaStreamWaitEvent(s_side, e_fork, 0);
    cudaMemsetAsync(deg, 0, M * sizeof(int), s_side);
    hist_kernel<<<(E + 255) / 256, 256, 0, s_side>>>(tgt, deg, E);
    scan_bsum_kernel <<<NB, 1024, 0, s_side>>>(deg, bsum, M);
    scan_boff_kernel <<<1, 128, 0, s_side>>>(bsum, boff, NB);
    scan_write_kernel<<<NB, 1024, 0, s_side>>>(deg, boff, rowptr, cursor, M);
    fill_kernel<<<(E + 255) / 256, 256, 0, s_side>>>(src, tgt, ew, cursor, esw, E);
    cudaEventRecord(e_join, s_side);

    // ---- main stream: conversions + layer-0 GEMM (overlaps CSR build) ----
    {
        int n4 = M * F_IN / 4;
        convert_x_kernel<<<(n4 + 255) / 256, 256>>>(x, xf, n4);
        int tot = 128 * 256 + 128 * 128 + 128 * 128 + 64 * 128;
        convert_w_all_kernel<<<(tot + 255) / 256, 256>>>(W0, w0, W1, w1, W2, w2, W3, w3);
    }
    gemm_mma_kernel<F_IN, F_HID, 128, 1><<<G128, 256, SMEM_128>>>(xf, w0, b0, hh, M, NTILES);

    // ---- join: agg0 needs both GEMM0 and the CSR ----
    cudaStreamWaitEvent(0, e_join, 0);
    agg128_kernel<0><<<agg_blocks, 256>>>(hh, rowptr, esw, nullptr, act0, M);

    // ---- layer 1 ----
    gemm_mma_kernel<F_HID, F_HID, 128, 1><<<G128, 256, SMEM_128>>>(act0, w1, b1, hh, M, NTILES);
    agg128_kernel<0><<<agg_blocks, 256>>>(hh, rowptr, esw, nullptr, act1, M);

    // ---- layer 2 (residual = act0) ----
    gemm_mma_kernel<F_HID, F_HID, 128, 1><<<G128, 256, SMEM_128>>>(act1, w2, b2, hh, M, NTILES);
    agg128_kernel<1><<<agg_blocks, 256>>>(hh, rowptr, esw, act0, act2, M);

    // ---- layer 3 (fp32 logits path) ----
    gemm_mma_kernel<F_HID, F_OUT, 64, 0><<<G64, 256, SMEM_64>>>(act2, w3, b3, h, M, NTILES);
    agg40_lsm_kernel<<<agg_blocks, 256>>>(h, rowptr, esw, out, M);
}